// round 1
// baseline (speedup 1.0000x reference)
#include <cuda_runtime.h>
#include <math.h>

// Problem constants
#define PB 2
#define PL 2048
#define PD 1024
#define PH 16
#define PDK 64
#define PM (PB * PL)   // 4096 rows when batch-flattened

// Scratch buffers (device globals: allocation-free, graph-capturable)
__device__ float g_q[PM * PD];
__device__ float g_k[PM * PD];
__device__ float g_v[PM * PD];
__device__ float g_attn[PM * PD];

// ---------------------------------------------------------------------------
// GEMM: C[m,n] = sum_k A[m,k] * Bm[n,k] + bias[n]
// A: [M,K] row-major, Bm: [N,K] row-major (i.e. C = A @ Bm^T + bias)
// 128x128x16 tiles, 256 threads, 8x8 per thread.
// Requires M%128==0, N%128==0, K%16==0 (true for all uses here).
// ---------------------------------------------------------------------------
__global__ __launch_bounds__(256) void gemm_nt_bias(
    const float* __restrict__ A, const float* __restrict__ Bm,
    const float* __restrict__ bias, float* __restrict__ C,
    int M, int N, int K)
{
    __shared__ float As[16][132];  // [k][m], padded
    __shared__ float Bs[16][132];  // [k][n], padded

    const int tid = threadIdx.x;
    const int bm = blockIdx.y * 128;
    const int bn = blockIdx.x * 128;

    float acc[8][8];
#pragma unroll
    for (int i = 0; i < 8; ++i)
#pragma unroll
        for (int j = 0; j < 8; ++j) acc[i][j] = 0.0f;

    const int lrow = tid >> 2;          // 0..63
    const int lcol = (tid & 3) << 2;    // 0,4,8,12
    const int tm = (tid >> 4) << 3;     // 0..120
    const int tn = (tid & 15) << 3;     // 0..120

    for (int k0 = 0; k0 < K; k0 += 16) {
#pragma unroll
        for (int it = 0; it < 2; ++it) {
            const int r = lrow + it * 64;
            float4 a4 = *(const float4*)(A + (size_t)(bm + r) * K + k0 + lcol);
            As[lcol + 0][r] = a4.x;
            As[lcol + 1][r] = a4.y;
            As[lcol + 2][r] = a4.z;
            As[lcol + 3][r] = a4.w;
            float4 b4 = *(const float4*)(Bm + (size_t)(bn + r) * K + k0 + lcol);
            Bs[lcol + 0][r] = b4.x;
            Bs[lcol + 1][r] = b4.y;
            Bs[lcol + 2][r] = b4.z;
            Bs[lcol + 3][r] = b4.w;
        }
        __syncthreads();

#pragma unroll
        for (int k = 0; k < 16; ++k) {
            float a[8], b[8];
            *(float4*)&a[0] = *(const float4*)&As[k][tm];
            *(float4*)&a[4] = *(const float4*)&As[k][tm + 4];
            *(float4*)&b[0] = *(const float4*)&Bs[k][tn];
            *(float4*)&b[4] = *(const float4*)&Bs[k][tn + 4];
#pragma unroll
            for (int i = 0; i < 8; ++i)
#pragma unroll
                for (int j = 0; j < 8; ++j)
                    acc[i][j] = fmaf(a[i], b[j], acc[i][j]);
        }
        __syncthreads();
    }

    float bv[8];
    *(float4*)&bv[0] = *(const float4*)(bias + bn + tn);
    *(float4*)&bv[4] = *(const float4*)(bias + bn + tn + 4);

#pragma unroll
    for (int i = 0; i < 8; ++i) {
        float4 c0 = make_float4(acc[i][0] + bv[0], acc[i][1] + bv[1],
                                acc[i][2] + bv[2], acc[i][3] + bv[3]);
        float4 c1 = make_float4(acc[i][4] + bv[4], acc[i][5] + bv[5],
                                acc[i][6] + bv[6], acc[i][7] + bv[7]);
        float* crow = C + (size_t)(bm + tm + i) * N + bn + tn;
        *(float4*)(crow) = c0;
        *(float4*)(crow + 4) = c1;
    }
}

// ---------------------------------------------------------------------------
// Causal flash attention, fp32, DK=64.
// grid = (L/64 q-tiles, B*H), block = 256 threads (16x16), 4x4 fragments.
// Online softmax; KV tiles strictly above the diagonal are skipped.
// Dynamic smem: qs[64*64] + ks[64*65] + vs[64*65] + ps[64*64].
// ---------------------------------------------------------------------------
#define FA_SMEM ((64 * 64 + 64 * 65 + 64 * 65 + 64 * 64) * sizeof(float))

__global__ __launch_bounds__(256) void flash_attn_causal(
    const float* __restrict__ gq, const float* __restrict__ gk,
    const float* __restrict__ gv, float* __restrict__ go)
{
    extern __shared__ float sm[];
    float* qs = sm;                 // stride 64
    float* ks = sm + 64 * 64;       // stride 65
    float* vs = ks + 64 * 65;       // stride 65
    float* ps = vs + 64 * 65;       // stride 64

    const int tid = threadIdx.x;
    const int tx = tid & 15;        // n / d fragment index
    const int ty = tid >> 4;        // m fragment index
    const int qt = blockIdx.x;      // query tile (0..31)
    const int b = blockIdx.y >> 4;
    const int h = blockIdx.y & 15;

    const size_t base = (size_t)b * PL * PD + (size_t)h * PDK;
    const float* qb = gq + base + (size_t)qt * 64 * PD;

    // Load Q tile [64 rows][64 head-cols]
#pragma unroll
    for (int it = 0; it < 4; ++it) {
        const int idx = tid + it * 256;
        const int r = idx >> 4;
        const int c = (idx & 15) << 2;
        *(float4*)&qs[r * 64 + c] = *(const float4*)(qb + (size_t)r * PD + c);
    }

    float mrow[4], lrow[4], o[4][4];
#pragma unroll
    for (int i = 0; i < 4; ++i) {
        mrow[i] = -3.0e38f;
        lrow[i] = 0.0f;
#pragma unroll
        for (int j = 0; j < 4; ++j) o[i][j] = 0.0f;
    }

    const float scale = 0.125f;  // 1/sqrt(64)

    for (int j = 0; j <= qt; ++j) {
        const float* kb = gk + base + (size_t)j * 64 * PD;
        const float* vb = gv + base + (size_t)j * 64 * PD;
#pragma unroll
        for (int it = 0; it < 4; ++it) {
            const int idx = tid + it * 256;
            const int r = idx >> 4;
            const int c = (idx & 15) << 2;
            float4 kvv = *(const float4*)(kb + (size_t)r * PD + c);
            ks[r * 65 + c + 0] = kvv.x;
            ks[r * 65 + c + 1] = kvv.y;
            ks[r * 65 + c + 2] = kvv.z;
            ks[r * 65 + c + 3] = kvv.w;
            float4 vvv = *(const float4*)(vb + (size_t)r * PD + c);
            vs[r * 65 + c + 0] = vvv.x;
            vs[r * 65 + c + 1] = vvv.y;
            vs[r * 65 + c + 2] = vvv.z;
            vs[r * 65 + c + 3] = vvv.w;
        }
        __syncthreads();

        // S = Q K^T (4x4 fragment per thread)
        float s[4][4];
#pragma unroll
        for (int i = 0; i < 4; ++i)
#pragma unroll
            for (int jj = 0; jj < 4; ++jj) s[i][jj] = 0.0f;

#pragma unroll 16
        for (int d = 0; d < 64; ++d) {
            float qv[4], kv[4];
#pragma unroll
            for (int i = 0; i < 4; ++i) qv[i] = qs[(ty * 4 + i) * 64 + d];
#pragma unroll
            for (int jj = 0; jj < 4; ++jj) kv[jj] = ks[(tx * 4 + jj) * 65 + d];
#pragma unroll
            for (int i = 0; i < 4; ++i)
#pragma unroll
                for (int jj = 0; jj < 4; ++jj)
                    s[i][jj] = fmaf(qv[i], kv[jj], s[i][jj]);
        }

        // Scale + causal mask (only the diagonal tile needs masking)
        const bool diag = (j == qt);
#pragma unroll
        for (int i = 0; i < 4; ++i)
#pragma unroll
            for (int jj = 0; jj < 4; ++jj) {
                float val = s[i][jj] * scale;
                if (diag && (tx * 4 + jj) > (ty * 4 + i)) val = -3.0e38f;
                s[i][jj] = val;
            }

        // Online softmax update
        float mnew[4], corr[4], p[4][4];
#pragma unroll
        for (int i = 0; i < 4; ++i) {
            float rm = fmaxf(fmaxf(s[i][0], s[i][1]), fmaxf(s[i][2], s[i][3]));
#pragma unroll
            for (int off = 8; off > 0; off >>= 1)
                rm = fmaxf(rm, __shfl_xor_sync(0xffffffffu, rm, off));
            mnew[i] = fmaxf(mrow[i], rm);
            corr[i] = __expf(mrow[i] - mnew[i]);
            mrow[i] = mnew[i];
        }
#pragma unroll
        for (int i = 0; i < 4; ++i) {
            float rs = 0.0f;
#pragma unroll
            for (int jj = 0; jj < 4; ++jj) {
                p[i][jj] = __expf(s[i][jj] - mnew[i]);
                rs += p[i][jj];
            }
#pragma unroll
            for (int off = 8; off > 0; off >>= 1)
                rs += __shfl_xor_sync(0xffffffffu, rs, off);
            lrow[i] = lrow[i] * corr[i] + rs;
#pragma unroll
            for (int jj = 0; jj < 4; ++jj) o[i][jj] *= corr[i];
        }

        // Stage P to smem for the PV GEMM
#pragma unroll
        for (int i = 0; i < 4; ++i)
            *(float4*)&ps[(ty * 4 + i) * 64 + tx * 4] =
                make_float4(p[i][0], p[i][1], p[i][2], p[i][3]);
        __syncthreads();

        // O += P @ V
#pragma unroll 16
        for (int n = 0; n < 64; ++n) {
            float pv[4], vv[4];
#pragma unroll
            for (int i = 0; i < 4; ++i) pv[i] = ps[(ty * 4 + i) * 64 + n];
#pragma unroll
            for (int jj = 0; jj < 4; ++jj) vv[jj] = vs[n * 65 + tx * 4 + jj];
#pragma unroll
            for (int i = 0; i < 4; ++i)
#pragma unroll
                for (int jj = 0; jj < 4; ++jj)
                    o[i][jj] = fmaf(pv[i], vv[jj], o[i][jj]);
        }
        __syncthreads();
    }

    // Epilogue: normalize + store
    float* ob = go + base + (size_t)qt * 64 * PD;
#pragma unroll
    for (int i = 0; i < 4; ++i) {
        const float inv = 1.0f / lrow[i];
        float4 r = make_float4(o[i][0] * inv, o[i][1] * inv,
                               o[i][2] * inv, o[i][3] * inv);
        *(float4*)(ob + (size_t)(ty * 4 + i) * PD + tx * 4) = r;
    }
}

// ---------------------------------------------------------------------------
extern "C" void kernel_launch(void* const* d_in, const int* in_sizes, int n_in,
                              void* d_out, int out_size)
{
    const float* Q    = (const float*)d_in[0];
    const float* K    = (const float*)d_in[1];
    const float* V    = (const float*)d_in[2];
    // d_in[3] = mask (causal, static) -- handled analytically in-kernel
    const float* Wq_w = (const float*)d_in[4];
    const float* Wq_b = (const float*)d_in[5];
    const float* Wk_w = (const float*)d_in[6];
    const float* Wk_b = (const float*)d_in[7];
    const float* Wv_w = (const float*)d_in[8];
    const float* Wv_b = (const float*)d_in[9];
    const float* fc_w = (const float*)d_in[10];
    const float* fc_b = (const float*)d_in[11];
    float* out = (float*)d_out;

    float *gq, *gk, *gv, *ga;
    cudaGetSymbolAddress((void**)&gq, g_q);
    cudaGetSymbolAddress((void**)&gk, g_k);
    cudaGetSymbolAddress((void**)&gv, g_v);
    cudaGetSymbolAddress((void**)&ga, g_attn);

    dim3 ggrid(PD / 128, PM / 128);  // (8, 32)

    gemm_nt_bias<<<ggrid, 256>>>(Q, Wq_w, Wq_b, gq, PM, PD, PD);
    gemm_nt_bias<<<ggrid, 256>>>(K, Wk_w, Wk_b, gk, PM, PD, PD);
    gemm_nt_bias<<<ggrid, 256>>>(V, Wv_w, Wv_b, gv, PM, PD, PD);

    cudaFuncSetAttribute(flash_attn_causal,
                         cudaFuncAttributeMaxDynamicSharedMemorySize,
                         (int)FA_SMEM);
    flash_attn_causal<<<dim3(PL / 64, PB * PH), 256, FA_SMEM>>>(gq, gk, gv, ga);

    gemm_nt_bias<<<ggrid, 256>>>(ga, fc_w, fc_b, out, PM, PD, PD);
}

// round 3
// speedup vs baseline: 1.2313x; 1.2313x over previous
#include <cuda_runtime.h>
#include <cuda_bf16.h>
#include <mma.h>
#include <cstdint>
#include <math.h>

using namespace nvcuda;

// Problem constants
#define PB 2
#define PL 2048
#define PD 1024
#define PH 16
#define PDK 64
#define PM (PB * PL)   // 4096

// Scratch (device globals: allocation-free, graph-capturable)
__device__ float g_q[PM * PD];
__device__ float g_k[PM * PD];
__device__ float g_v[PM * PD];
__device__ float g_attn[PM * PD];
__device__ __nv_bfloat16 g_ahi[PM * PD];
__device__ __nv_bfloat16 g_alo[PM * PD];
__device__ __nv_bfloat16 g_whi[PD * PD];
__device__ __nv_bfloat16 g_wlo[PD * PD];

// ---------------------------------------------------------------------------
// Split fp32 -> (bf16 hi, bf16 lo):  x = hi + lo + O(2^-17 x)
// ---------------------------------------------------------------------------
__global__ __launch_bounds__(256) void split_bf16(
    const float* __restrict__ x,
    __nv_bfloat16* __restrict__ hi, __nv_bfloat16* __restrict__ lo, int n4)
{
    int i = blockIdx.x * 256 + threadIdx.x;
    if (i >= n4) return;
    float4 v = reinterpret_cast<const float4*>(x)[i];
    float vv[4] = {v.x, v.y, v.z, v.w};
    unsigned short hs[4], ls[4];
#pragma unroll
    for (int j = 0; j < 4; ++j) {
        __nv_bfloat16 h = __float2bfloat16(vv[j]);
        float r = vv[j] - __bfloat162float(h);
        __nv_bfloat16 l = __float2bfloat16(r);
        hs[j] = __bfloat16_as_ushort(h);
        ls[j] = __bfloat16_as_ushort(l);
    }
    reinterpret_cast<uint2*>(hi)[i] =
        make_uint2((uint32_t)hs[0] | ((uint32_t)hs[1] << 16),
                   (uint32_t)hs[2] | ((uint32_t)hs[3] << 16));
    reinterpret_cast<uint2*>(lo)[i] =
        make_uint2((uint32_t)ls[0] | ((uint32_t)ls[1] << 16),
                   (uint32_t)ls[2] | ((uint32_t)ls[3] << 16));
}

// ---------------------------------------------------------------------------
// wmma bf16 GEMM (3-term split): C[m,n] = sum_k A[m,k]*B[n,k] + bias[n]
// Block tile 128x128, 8 warps (4M x 2N), warp tile 32x64 (2x4 wmma frags).
// K-chunks of 32, double-buffered smem (padded stride 40 bf16), LDG->reg
// staging overlapped with wmma compute, one __syncthreads per chunk.
// ---------------------------------------------------------------------------
#define GTM 128
#define GTN 128
#define GTK 32
#define SPITCH 40                         // bf16 elements per smem row
#define TILE_B (128 * SPITCH * 2)         // 10240 bytes per (128 x 32) tile
#define STAGE_B (4 * TILE_B)              // Ahi,Alo,Bhi,Blo = 40960
#define GEMM_DSMEM (2 * STAGE_B)          // 81920

__global__ __launch_bounds__(256, 1) void gemm3_wmma(
    const __nv_bfloat16* __restrict__ Ahi, const __nv_bfloat16* __restrict__ Alo,
    const __nv_bfloat16* __restrict__ Bhi, const __nv_bfloat16* __restrict__ Blo,
    const float* __restrict__ bias, float* __restrict__ C, int K, int N)
{
    extern __shared__ char dsm[];
    __shared__ float sbias[GTN];

    const int tid = threadIdx.x;
    const int wid = tid >> 5;
    const int lane = tid & 31;
    const int wm = wid & 3;       // warp row (4)
    const int wn = wid >> 2;      // warp col (2)
    const int bm = blockIdx.y * GTM;
    const int bn = blockIdx.x * GTN;

    if (tid < GTN) sbias[tid] = bias[bn + tid];

    wmma::fragment<wmma::accumulator, 16, 16, 16, float> acc[2][4];
#pragma unroll
    for (int i = 0; i < 2; ++i)
#pragma unroll
        for (int j = 0; j < 4; ++j) wmma::fill_fragment(acc[i][j], 0.0f);

    // smem tile pointers for stage s
    auto sAhi = [&](int s) { return (__nv_bfloat16*)(dsm + s * STAGE_B); };
    auto sAlo = [&](int s) { return (__nv_bfloat16*)(dsm + s * STAGE_B + TILE_B); };
    auto sBhi = [&](int s) { return (__nv_bfloat16*)(dsm + s * STAGE_B + 2 * TILE_B); };
    auto sBlo = [&](int s) { return (__nv_bfloat16*)(dsm + s * STAGE_B + 3 * TILE_B); };

    // per-thread load mapping: 2 iterations x 8 bf16 per tile
    const int r0 = tid >> 2;               // 0..63
    const int c0 = (tid & 3) * 8;          // 0,8,16,24

    // prologue: load chunk 0 into stage 0
#pragma unroll
    for (int it = 0; it < 2; ++it) {
        const int r = r0 + it * 64;
        const size_t goA = (size_t)(bm + r) * K + c0;
        const size_t goB = (size_t)(bn + r) * K + c0;
        *(uint4*)(sAhi(0) + r * SPITCH + c0) = *(const uint4*)(Ahi + goA);
        *(uint4*)(sAlo(0) + r * SPITCH + c0) = *(const uint4*)(Alo + goA);
        *(uint4*)(sBhi(0) + r * SPITCH + c0) = *(const uint4*)(Bhi + goB);
        *(uint4*)(sBlo(0) + r * SPITCH + c0) = *(const uint4*)(Blo + goB);
    }
    __syncthreads();

    const int nchunk = K / GTK;    // 32
    for (int c = 0; c < nchunk; ++c) {
        const int s = c & 1;
        uint4 stg[8];
        if (c + 1 < nchunk) {
            const int k1 = (c + 1) * GTK;
#pragma unroll
            for (int it = 0; it < 2; ++it) {
                const int r = r0 + it * 64;
                const size_t goA = (size_t)(bm + r) * K + k1 + c0;
                const size_t goB = (size_t)(bn + r) * K + k1 + c0;
                stg[it * 4 + 0] = *(const uint4*)(Ahi + goA);
                stg[it * 4 + 1] = *(const uint4*)(Alo + goA);
                stg[it * 4 + 2] = *(const uint4*)(Bhi + goB);
                stg[it * 4 + 3] = *(const uint4*)(Blo + goB);
            }
        }

        // compute on stage s: 2 k-steps of 16
        const __nv_bfloat16* pAhi = sAhi(s) + wm * 32 * SPITCH;
        const __nv_bfloat16* pAlo = sAlo(s) + wm * 32 * SPITCH;
        const __nv_bfloat16* pBhi = sBhi(s) + wn * 64 * SPITCH;
        const __nv_bfloat16* pBlo = sBlo(s) + wn * 64 * SPITCH;
#pragma unroll
        for (int kk = 0; kk < 2; ++kk) {
            wmma::fragment<wmma::matrix_a, 16, 16, 16, __nv_bfloat16, wmma::row_major> fahi[2], falo[2];
#pragma unroll
            for (int i = 0; i < 2; ++i) {
                wmma::load_matrix_sync(fahi[i], pAhi + i * 16 * SPITCH + kk * 16, SPITCH);
                wmma::load_matrix_sync(falo[i], pAlo + i * 16 * SPITCH + kk * 16, SPITCH);
            }
#pragma unroll
            for (int j = 0; j < 4; ++j) {
                wmma::fragment<wmma::matrix_b, 16, 16, 16, __nv_bfloat16, wmma::col_major> fbhi, fblo;
                wmma::load_matrix_sync(fbhi, pBhi + j * 16 * SPITCH + kk * 16, SPITCH);
                wmma::load_matrix_sync(fblo, pBlo + j * 16 * SPITCH + kk * 16, SPITCH);
#pragma unroll
                for (int i = 0; i < 2; ++i) {
                    wmma::mma_sync(acc[i][j], fahi[i], fbhi, acc[i][j]);
                    wmma::mma_sync(acc[i][j], fahi[i], fblo, acc[i][j]);
                    wmma::mma_sync(acc[i][j], falo[i], fbhi, acc[i][j]);
                }
            }
        }

        if (c + 1 < nchunk) {
            const int s1 = 1 - s;
#pragma unroll
            for (int it = 0; it < 2; ++it) {
                const int r = r0 + it * 64;
                *(uint4*)(sAhi(s1) + r * SPITCH + c0) = stg[it * 4 + 0];
                *(uint4*)(sAlo(s1) + r * SPITCH + c0) = stg[it * 4 + 1];
                *(uint4*)(sBhi(s1) + r * SPITCH + c0) = stg[it * 4 + 2];
                *(uint4*)(sBlo(s1) + r * SPITCH + c0) = stg[it * 4 + 3];
            }
        }
        __syncthreads();
    }

    // Epilogue: stage accum through smem (reuse tile buffers), add bias, store
    float* ws = (float*)dsm + wid * (32 * 64);   // 8 KB per warp, 64 KB total
#pragma unroll
    for (int i = 0; i < 2; ++i)
#pragma unroll
        for (int j = 0; j < 4; ++j)
            wmma::store_matrix_sync(ws + i * 16 * 64 + j * 16, acc[i][j], 64,
                                    wmma::mem_row_major);
    __syncwarp();

    const int m = bm + wm * 32 + lane;
    float* crow = C + (size_t)m * N + bn + wn * 64;
    const float* wrow = ws + lane * 64;
    const float* brow = sbias + wn * 64;
#pragma unroll
    for (int cc = 0; cc < 16; ++cc) {
        float4 v = *(const float4*)(wrow + cc * 4);
        v.x += brow[cc * 4 + 0];
        v.y += brow[cc * 4 + 1];
        v.z += brow[cc * 4 + 2];
        v.w += brow[cc * 4 + 3];
        *(float4*)(crow + cc * 4) = v;
    }
}

// ---------------------------------------------------------------------------
// Causal flash attention, fp32, DK=64 (unchanged from round 1).
// ---------------------------------------------------------------------------
#define FA_SMEM ((64 * 64 + 64 * 65 + 64 * 65 + 64 * 64) * sizeof(float))

__global__ __launch_bounds__(256) void flash_attn_causal(
    const float* __restrict__ gq, const float* __restrict__ gk,
    const float* __restrict__ gv, float* __restrict__ go)
{
    extern __shared__ float sm[];
    float* qs = sm;
    float* ks = sm + 64 * 64;
    float* vs = ks + 64 * 65;
    float* ps = vs + 64 * 65;

    const int tid = threadIdx.x;
    const int tx = tid & 15;
    const int ty = tid >> 4;
    const int qt = blockIdx.x;
    const int b = blockIdx.y >> 4;
    const int h = blockIdx.y & 15;

    const size_t base = (size_t)b * PL * PD + (size_t)h * PDK;
    const float* qb = gq + base + (size_t)qt * 64 * PD;

#pragma unroll
    for (int it = 0; it < 4; ++it) {
        const int idx = tid + it * 256;
        const int r = idx >> 4;
        const int c = (idx & 15) << 2;
        *(float4*)&qs[r * 64 + c] = *(const float4*)(qb + (size_t)r * PD + c);
    }

    float mrow[4], lrow[4], o[4][4];
#pragma unroll
    for (int i = 0; i < 4; ++i) {
        mrow[i] = -3.0e38f;
        lrow[i] = 0.0f;
#pragma unroll
        for (int j = 0; j < 4; ++j) o[i][j] = 0.0f;
    }

    const float scale = 0.125f;

    for (int j = 0; j <= qt; ++j) {
        const float* kb = gk + base + (size_t)j * 64 * PD;
        const float* vb = gv + base + (size_t)j * 64 * PD;
#pragma unroll
        for (int it = 0; it < 4; ++it) {
            const int idx = tid + it * 256;
            const int r = idx >> 4;
            const int c = (idx & 15) << 2;
            float4 kvv = *(const float4*)(kb + (size_t)r * PD + c);
            ks[r * 65 + c + 0] = kvv.x;
            ks[r * 65 + c + 1] = kvv.y;
            ks[r * 65 + c + 2] = kvv.z;
            ks[r * 65 + c + 3] = kvv.w;
            float4 vvv = *(const float4*)(vb + (size_t)r * PD + c);
            vs[r * 65 + c + 0] = vvv.x;
            vs[r * 65 + c + 1] = vvv.y;
            vs[r * 65 + c + 2] = vvv.z;
            vs[r * 65 + c + 3] = vvv.w;
        }
        __syncthreads();

        float s[4][4];
#pragma unroll
        for (int i = 0; i < 4; ++i)
#pragma unroll
            for (int jj = 0; jj < 4; ++jj) s[i][jj] = 0.0f;

#pragma unroll 16
        for (int d = 0; d < 64; ++d) {
            float qv[4], kv[4];
#pragma unroll
            for (int i = 0; i < 4; ++i) qv[i] = qs[(ty * 4 + i) * 64 + d];
#pragma unroll
            for (int jj = 0; jj < 4; ++jj) kv[jj] = ks[(tx * 4 + jj) * 65 + d];
#pragma unroll
            for (int i = 0; i < 4; ++i)
#pragma unroll
                for (int jj = 0; jj < 4; ++jj)
                    s[i][jj] = fmaf(qv[i], kv[jj], s[i][jj]);
        }

        const bool diag = (j == qt);
#pragma unroll
        for (int i = 0; i < 4; ++i)
#pragma unroll
            for (int jj = 0; jj < 4; ++jj) {
                float val = s[i][jj] * scale;
                if (diag && (tx * 4 + jj) > (ty * 4 + i)) val = -3.0e38f;
                s[i][jj] = val;
            }

        float mnew[4], corr[4], p[4][4];
#pragma unroll
        for (int i = 0; i < 4; ++i) {
            float rm = fmaxf(fmaxf(s[i][0], s[i][1]), fmaxf(s[i][2], s[i][3]));
#pragma unroll
            for (int off = 8; off > 0; off >>= 1)
                rm = fmaxf(rm, __shfl_xor_sync(0xffffffffu, rm, off));
            mnew[i] = fmaxf(mrow[i], rm);
            corr[i] = __expf(mrow[i] - mnew[i]);
            mrow[i] = mnew[i];
        }
#pragma unroll
        for (int i = 0; i < 4; ++i) {
            float rs = 0.0f;
#pragma unroll
            for (int jj = 0; jj < 4; ++jj) {
                p[i][jj] = __expf(s[i][jj] - mnew[i]);
                rs += p[i][jj];
            }
#pragma unroll
            for (int off = 8; off > 0; off >>= 1)
                rs += __shfl_xor_sync(0xffffffffu, rs, off);
            lrow[i] = lrow[i] * corr[i] + rs;
#pragma unroll
            for (int jj = 0; jj < 4; ++jj) o[i][jj] *= corr[i];
        }

#pragma unroll
        for (int i = 0; i < 4; ++i)
            *(float4*)&ps[(ty * 4 + i) * 64 + tx * 4] =
                make_float4(p[i][0], p[i][1], p[i][2], p[i][3]);
        __syncthreads();

#pragma unroll 16
        for (int n = 0; n < 64; ++n) {
            float pv[4], vv[4];
#pragma unroll
            for (int i = 0; i < 4; ++i) pv[i] = ps[(ty * 4 + i) * 64 + n];
#pragma unroll
            for (int jj = 0; jj < 4; ++jj) vv[jj] = vs[n * 65 + tx * 4 + jj];
#pragma unroll
            for (int i = 0; i < 4; ++i)
#pragma unroll
                for (int jj = 0; jj < 4; ++jj)
                    o[i][jj] = fmaf(pv[i], vv[jj], o[i][jj]);
        }
        __syncthreads();
    }

    float* ob = go + base + (size_t)qt * 64 * PD;
#pragma unroll
    for (int i = 0; i < 4; ++i) {
        const float inv = 1.0f / lrow[i];
        float4 r = make_float4(o[i][0] * inv, o[i][1] * inv,
                               o[i][2] * inv, o[i][3] * inv);
        *(float4*)(ob + (size_t)(ty * 4 + i) * PD + tx * 4) = r;
    }
}

// ---------------------------------------------------------------------------
extern "C" void kernel_launch(void* const* d_in, const int* in_sizes, int n_in,
                              void* d_out, int out_size)
{
    const float* Q    = (const float*)d_in[0];
    const float* K    = (const float*)d_in[1];
    const float* V    = (const float*)d_in[2];
    const float* Wq_w = (const float*)d_in[4];
    const float* Wq_b = (const float*)d_in[5];
    const float* Wk_w = (const float*)d_in[6];
    const float* Wk_b = (const float*)d_in[7];
    const float* Wv_w = (const float*)d_in[8];
    const float* Wv_b = (const float*)d_in[9];
    const float* fc_w = (const float*)d_in[10];
    const float* fc_b = (const float*)d_in[11];
    float* out = (float*)d_out;

    float *gq, *gk, *gv, *ga;
    __nv_bfloat16 *ahi, *alo, *whi, *wlo;
    cudaGetSymbolAddress((void**)&gq, g_q);
    cudaGetSymbolAddress((void**)&gk, g_k);
    cudaGetSymbolAddress((void**)&gv, g_v);
    cudaGetSymbolAddress((void**)&ga, g_attn);
    cudaGetSymbolAddress((void**)&ahi, g_ahi);
    cudaGetSymbolAddress((void**)&alo, g_alo);
    cudaGetSymbolAddress((void**)&whi, g_whi);
    cudaGetSymbolAddress((void**)&wlo, g_wlo);

    cudaFuncSetAttribute(gemm3_wmma,
                         cudaFuncAttributeMaxDynamicSharedMemorySize, GEMM_DSMEM);
    cudaFuncSetAttribute(flash_attn_causal,
                         cudaFuncAttributeMaxDynamicSharedMemorySize, (int)FA_SMEM);

    const int nA4 = PM * PD / 4;
    const int nW4 = PD * PD / 4;
    dim3 ggrid(PD / GTN, PM / GTM);   // (8, 32) = 256 CTAs

    // Q projection
    split_bf16<<<nA4 / 256, 256>>>(Q, ahi, alo, nA4);
    split_bf16<<<nW4 / 256, 256>>>(Wq_w, whi, wlo, nW4);
    gemm3_wmma<<<ggrid, 256, GEMM_DSMEM>>>(ahi, alo, whi, wlo, Wq_b, gq, PD, PD);
    // K projection
    split_bf16<<<nA4 / 256, 256>>>(K, ahi, alo, nA4);
    split_bf16<<<nW4 / 256, 256>>>(Wk_w, whi, wlo, nW4);
    gemm3_wmma<<<ggrid, 256, GEMM_DSMEM>>>(ahi, alo, whi, wlo, Wk_b, gk, PD, PD);
    // V projection
    split_bf16<<<nA4 / 256, 256>>>(V, ahi, alo, nA4);
    split_bf16<<<nW4 / 256, 256>>>(Wv_w, whi, wlo, nW4);
    gemm3_wmma<<<ggrid, 256, GEMM_DSMEM>>>(ahi, alo, whi, wlo, Wv_b, gv, PD, PD);

    // Attention (fp32)
    flash_attn_causal<<<dim3(PL / 64, PB * PH), 256, FA_SMEM>>>(gq, gk, gv, ga);

    // Output projection
    split_bf16<<<nA4 / 256, 256>>>(ga, ahi, alo, nA4);
    split_bf16<<<nW4 / 256, 256>>>(fc_w, whi, wlo, nW4);
    gemm3_wmma<<<ggrid, 256, GEMM_DSMEM>>>(ahi, alo, whi, wlo, fc_b, out, PD, PD);
}

// round 4
// speedup vs baseline: 1.3055x; 1.0603x over previous
#include <cuda_runtime.h>
#include <cuda_bf16.h>
#include <mma.h>
#include <cstdint>
#include <math.h>

using namespace nvcuda;

// Problem constants
#define PB 2
#define PL 2048
#define PD 1024
#define PH 16
#define PDK 64
#define PM (PB * PL)   // 4096

// Scratch (device globals: allocation-free, graph-capturable)
__device__ __nv_bfloat16 g_ihi[PM * PD];
__device__ __nv_bfloat16 g_ilo[PM * PD];
__device__ __nv_bfloat16 g_whi[PD * PD];
__device__ __nv_bfloat16 g_wlo[PD * PD];
__device__ __nv_bfloat16 g_qhi[PM * PD];
__device__ __nv_bfloat16 g_qlo[PM * PD];
__device__ __nv_bfloat16 g_khi[PM * PD];
__device__ __nv_bfloat16 g_klo[PM * PD];
__device__ __nv_bfloat16 g_vhi[PM * PD];
__device__ __nv_bfloat16 g_vlo[PM * PD];
__device__ __nv_bfloat16 g_ahi[PM * PD];
__device__ __nv_bfloat16 g_alo[PM * PD];

// ---------------------------------------------------------------------------
// Split fp32 -> (bf16 hi, bf16 lo)
// ---------------------------------------------------------------------------
__global__ __launch_bounds__(256) void split_bf16(
    const float* __restrict__ x,
    __nv_bfloat16* __restrict__ hi, __nv_bfloat16* __restrict__ lo, int n4)
{
    int i = blockIdx.x * 256 + threadIdx.x;
    if (i >= n4) return;
    float4 v = reinterpret_cast<const float4*>(x)[i];
    float vv[4] = {v.x, v.y, v.z, v.w};
    unsigned short hs[4], ls[4];
#pragma unroll
    for (int j = 0; j < 4; ++j) {
        __nv_bfloat16 h = __float2bfloat16(vv[j]);
        float r = vv[j] - __bfloat162float(h);
        __nv_bfloat16 l = __float2bfloat16(r);
        hs[j] = __bfloat16_as_ushort(h);
        ls[j] = __bfloat16_as_ushort(l);
    }
    reinterpret_cast<uint2*>(hi)[i] =
        make_uint2((uint32_t)hs[0] | ((uint32_t)hs[1] << 16),
                   (uint32_t)hs[2] | ((uint32_t)hs[3] << 16));
    reinterpret_cast<uint2*>(lo)[i] =
        make_uint2((uint32_t)ls[0] | ((uint32_t)ls[1] << 16),
                   (uint32_t)ls[2] | ((uint32_t)ls[3] << 16));
}

// ---------------------------------------------------------------------------
// wmma bf16 GEMM (3-term split): C[m,n] = sum_k A[m,k]*B[n,k] + bias[n]
// SPLIT=true: write bf16 hi/lo pair instead of fp32.
// ---------------------------------------------------------------------------
#define GTM 128
#define GTN 128
#define GTK 32
#define SPITCH 40
#define TILE_B (128 * SPITCH * 2)
#define STAGE_B (4 * TILE_B)
#define GEMM_DSMEM (2 * STAGE_B)

template <bool SPLIT>
__global__ __launch_bounds__(256, 1) void gemm3_wmma(
    const __nv_bfloat16* __restrict__ Ahi, const __nv_bfloat16* __restrict__ Alo,
    const __nv_bfloat16* __restrict__ Bhi, const __nv_bfloat16* __restrict__ Blo,
    const float* __restrict__ bias, float* __restrict__ C,
    __nv_bfloat16* __restrict__ Chi, __nv_bfloat16* __restrict__ Clo,
    int K, int N)
{
    extern __shared__ char dsm[];
    __shared__ float sbias[GTN];

    const int tid = threadIdx.x;
    const int wid = tid >> 5;
    const int lane = tid & 31;
    const int wm = wid & 3;
    const int wn = wid >> 2;
    const int bm = blockIdx.y * GTM;
    const int bn = blockIdx.x * GTN;

    if (tid < GTN) sbias[tid] = bias[bn + tid];

    wmma::fragment<wmma::accumulator, 16, 16, 16, float> acc[2][4];
#pragma unroll
    for (int i = 0; i < 2; ++i)
#pragma unroll
        for (int j = 0; j < 4; ++j) wmma::fill_fragment(acc[i][j], 0.0f);

    auto sAhi = [&](int s) { return (__nv_bfloat16*)(dsm + s * STAGE_B); };
    auto sAlo = [&](int s) { return (__nv_bfloat16*)(dsm + s * STAGE_B + TILE_B); };
    auto sBhi = [&](int s) { return (__nv_bfloat16*)(dsm + s * STAGE_B + 2 * TILE_B); };
    auto sBlo = [&](int s) { return (__nv_bfloat16*)(dsm + s * STAGE_B + 3 * TILE_B); };

    const int r0 = tid >> 2;
    const int c0 = (tid & 3) * 8;

#pragma unroll
    for (int it = 0; it < 2; ++it) {
        const int r = r0 + it * 64;
        const size_t goA = (size_t)(bm + r) * K + c0;
        const size_t goB = (size_t)(bn + r) * K + c0;
        *(uint4*)(sAhi(0) + r * SPITCH + c0) = *(const uint4*)(Ahi + goA);
        *(uint4*)(sAlo(0) + r * SPITCH + c0) = *(const uint4*)(Alo + goA);
        *(uint4*)(sBhi(0) + r * SPITCH + c0) = *(const uint4*)(Bhi + goB);
        *(uint4*)(sBlo(0) + r * SPITCH + c0) = *(const uint4*)(Blo + goB);
    }
    __syncthreads();

    const int nchunk = K / GTK;
    for (int c = 0; c < nchunk; ++c) {
        const int s = c & 1;
        uint4 stg[8];
        if (c + 1 < nchunk) {
            const int k1 = (c + 1) * GTK;
#pragma unroll
            for (int it = 0; it < 2; ++it) {
                const int r = r0 + it * 64;
                const size_t goA = (size_t)(bm + r) * K + k1 + c0;
                const size_t goB = (size_t)(bn + r) * K + k1 + c0;
                stg[it * 4 + 0] = *(const uint4*)(Ahi + goA);
                stg[it * 4 + 1] = *(const uint4*)(Alo + goA);
                stg[it * 4 + 2] = *(const uint4*)(Bhi + goB);
                stg[it * 4 + 3] = *(const uint4*)(Blo + goB);
            }
        }

        const __nv_bfloat16* pAhi = sAhi(s) + wm * 32 * SPITCH;
        const __nv_bfloat16* pAlo = sAlo(s) + wm * 32 * SPITCH;
        const __nv_bfloat16* pBhi = sBhi(s) + wn * 64 * SPITCH;
        const __nv_bfloat16* pBlo = sBlo(s) + wn * 64 * SPITCH;
#pragma unroll
        for (int kk = 0; kk < 2; ++kk) {
            wmma::fragment<wmma::matrix_a, 16, 16, 16, __nv_bfloat16, wmma::row_major> fahi[2], falo[2];
#pragma unroll
            for (int i = 0; i < 2; ++i) {
                wmma::load_matrix_sync(fahi[i], pAhi + i * 16 * SPITCH + kk * 16, SPITCH);
                wmma::load_matrix_sync(falo[i], pAlo + i * 16 * SPITCH + kk * 16, SPITCH);
            }
#pragma unroll
            for (int j = 0; j < 4; ++j) {
                wmma::fragment<wmma::matrix_b, 16, 16, 16, __nv_bfloat16, wmma::col_major> fbhi, fblo;
                wmma::load_matrix_sync(fbhi, pBhi + j * 16 * SPITCH + kk * 16, SPITCH);
                wmma::load_matrix_sync(fblo, pBlo + j * 16 * SPITCH + kk * 16, SPITCH);
#pragma unroll
                for (int i = 0; i < 2; ++i) {
                    wmma::mma_sync(acc[i][j], fahi[i], fbhi, acc[i][j]);
                    wmma::mma_sync(acc[i][j], fahi[i], fblo, acc[i][j]);
                    wmma::mma_sync(acc[i][j], falo[i], fbhi, acc[i][j]);
                }
            }
        }

        if (c + 1 < nchunk) {
            const int s1 = 1 - s;
#pragma unroll
            for (int it = 0; it < 2; ++it) {
                const int r = r0 + it * 64;
                *(uint4*)(sAhi(s1) + r * SPITCH + c0) = stg[it * 4 + 0];
                *(uint4*)(sAlo(s1) + r * SPITCH + c0) = stg[it * 4 + 1];
                *(uint4*)(sBhi(s1) + r * SPITCH + c0) = stg[it * 4 + 2];
                *(uint4*)(sBlo(s1) + r * SPITCH + c0) = stg[it * 4 + 3];
            }
        }
        __syncthreads();
    }

    // Epilogue via smem
    float* ws = (float*)dsm + wid * (32 * 64);
#pragma unroll
    for (int i = 0; i < 2; ++i)
#pragma unroll
        for (int j = 0; j < 4; ++j)
            wmma::store_matrix_sync(ws + i * 16 * 64 + j * 16, acc[i][j], 64,
                                    wmma::mem_row_major);
    __syncwarp();

    const int m = bm + wm * 32 + lane;
    const size_t obase = (size_t)m * N + bn + wn * 64;
    const float* wrow = ws + lane * 64;
    const float* brow = sbias + wn * 64;
#pragma unroll
    for (int cc = 0; cc < 16; ++cc) {
        float4 v = *(const float4*)(wrow + cc * 4);
        v.x += brow[cc * 4 + 0];
        v.y += brow[cc * 4 + 1];
        v.z += brow[cc * 4 + 2];
        v.w += brow[cc * 4 + 3];
        if (SPLIT) {
            float vv[4] = {v.x, v.y, v.z, v.w};
            unsigned short hs[4], ls[4];
#pragma unroll
            for (int q = 0; q < 4; ++q) {
                __nv_bfloat16 h = __float2bfloat16(vv[q]);
                float r = vv[q] - __bfloat162float(h);
                __nv_bfloat16 l = __float2bfloat16(r);
                hs[q] = __bfloat16_as_ushort(h);
                ls[q] = __bfloat16_as_ushort(l);
            }
            *(uint2*)(Chi + obase + cc * 4) =
                make_uint2((uint32_t)hs[0] | ((uint32_t)hs[1] << 16),
                           (uint32_t)hs[2] | ((uint32_t)hs[3] << 16));
            *(uint2*)(Clo + obase + cc * 4) =
                make_uint2((uint32_t)ls[0] | ((uint32_t)ls[1] << 16),
                           (uint32_t)ls[2] | ((uint32_t)ls[3] << 16));
        } else {
            *(float4*)(C + obase + cc * 4) = v;
        }
    }
}

// ---------------------------------------------------------------------------
// Tensor-core causal flash attention, bf16 3-term split, DK=64.
// grid = (L/128, B*H), 256 threads (8 warps x 16 rows). KV tiles of 64.
// ---------------------------------------------------------------------------
#define APITCH 72
#define OFF_KHI 0
#define OFF_KLO 9216
#define OFF_VHI 18432
#define OFF_VLO 27648
#define OFF_S   36864            // float, 128 x 72
#define OFF_PHI 73728            // bf16, 128 x 72
#define OFF_PLO 92160
#define OFF_OQ  110592           // union: O (float 128x72) | Qhi+Qlo (bf16 128x72 each)
#define OFF_M   147456
#define OFF_L   147968
#define OFF_CR  148480
#define ATT_SMEM 148992

__global__ __launch_bounds__(256, 1) void flash_attn_tc(
    const __nv_bfloat16* __restrict__ qhi, const __nv_bfloat16* __restrict__ qlo,
    const __nv_bfloat16* __restrict__ khi, const __nv_bfloat16* __restrict__ klo,
    const __nv_bfloat16* __restrict__ vhi, const __nv_bfloat16* __restrict__ vlo,
    __nv_bfloat16* __restrict__ ohi, __nv_bfloat16* __restrict__ olo)
{
    extern __shared__ char dsm[];
    __nv_bfloat16* skhi = (__nv_bfloat16*)(dsm + OFF_KHI);
    __nv_bfloat16* sklo = (__nv_bfloat16*)(dsm + OFF_KLO);
    __nv_bfloat16* svhi = (__nv_bfloat16*)(dsm + OFF_VHI);
    __nv_bfloat16* svlo = (__nv_bfloat16*)(dsm + OFF_VLO);
    float* sS = (float*)(dsm + OFF_S);
    __nv_bfloat16* sphi = (__nv_bfloat16*)(dsm + OFF_PHI);
    __nv_bfloat16* splo = (__nv_bfloat16*)(dsm + OFF_PLO);
    float* sO = (float*)(dsm + OFF_OQ);
    __nv_bfloat16* sQhi = (__nv_bfloat16*)(dsm + OFF_OQ);
    __nv_bfloat16* sQlo = (__nv_bfloat16*)(dsm + OFF_OQ + 18432);
    float* sm_m = (float*)(dsm + OFF_M);
    float* sm_l = (float*)(dsm + OFF_L);
    float* sm_c = (float*)(dsm + OFF_CR);

    const int tid = threadIdx.x;
    const int w = tid >> 5;
    const int qt = blockIdx.x;
    const int b = blockIdx.y >> 4;
    const int h = blockIdx.y & 15;
    const size_t rowbase = (size_t)b * PL * PD + (size_t)h * PDK;

    // Load Q tile (128 rows x 64) hi/lo
#pragma unroll
    for (int it = 0; it < 4; ++it) {
        const int idx = tid + it * 256;
        const int r = idx >> 3;
        const int c = (idx & 7) * 8;
        const size_t g = rowbase + (size_t)(qt * 128 + r) * PD + c;
        *(uint4*)(sQhi + r * APITCH + c) = *(const uint4*)(qhi + g);
        *(uint4*)(sQlo + r * APITCH + c) = *(const uint4*)(qlo + g);
    }
    if (tid < 128) { sm_m[tid] = -3.0e38f; sm_l[tid] = 0.0f; }
    __syncthreads();

    // Cache Q fragments in registers (per warp: 16 rows, 4 k-chunks, hi/lo)
    wmma::fragment<wmma::matrix_a, 16, 16, 16, __nv_bfloat16, wmma::row_major> qh_f[4], ql_f[4];
#pragma unroll
    for (int kk = 0; kk < 4; ++kk) {
        wmma::load_matrix_sync(qh_f[kk], sQhi + (w * 16) * APITCH + kk * 16, APITCH);
        wmma::load_matrix_sync(ql_f[kk], sQlo + (w * 16) * APITCH + kk * 16, APITCH);
    }
    __syncthreads();

    const int jmax = 2 * qt + 1;
    for (int j = 0; j <= jmax; ++j) {
        // Load K/V tiles (64 rows x 64) hi/lo
#pragma unroll
        for (int it = 0; it < 2; ++it) {
            const int idx = tid + it * 256;
            const int r = idx >> 3;
            const int c = (idx & 7) * 8;
            const size_t g = rowbase + (size_t)(j * 64 + r) * PD + c;
            *(uint4*)(skhi + r * APITCH + c) = *(const uint4*)(khi + g);
            *(uint4*)(sklo + r * APITCH + c) = *(const uint4*)(klo + g);
            *(uint4*)(svhi + r * APITCH + c) = *(const uint4*)(vhi + g);
            *(uint4*)(svlo + r * APITCH + c) = *(const uint4*)(vlo + g);
        }
        __syncthreads();

        // S = Q K^T  (warp: 16 rows x 64 cols)
        {
            wmma::fragment<wmma::accumulator, 16, 16, 16, float> sacc[4];
#pragma unroll
            for (int n = 0; n < 4; ++n) wmma::fill_fragment(sacc[n], 0.0f);
#pragma unroll
            for (int kk = 0; kk < 4; ++kk) {
#pragma unroll
                for (int n = 0; n < 4; ++n) {
                    wmma::fragment<wmma::matrix_b, 16, 16, 16, __nv_bfloat16, wmma::col_major> kbh, kbl;
                    wmma::load_matrix_sync(kbh, skhi + (n * 16) * APITCH + kk * 16, APITCH);
                    wmma::load_matrix_sync(kbl, sklo + (n * 16) * APITCH + kk * 16, APITCH);
                    wmma::mma_sync(sacc[n], qh_f[kk], kbh, sacc[n]);
                    wmma::mma_sync(sacc[n], qh_f[kk], kbl, sacc[n]);
                    wmma::mma_sync(sacc[n], ql_f[kk], kbh, sacc[n]);
                }
            }
#pragma unroll
            for (int n = 0; n < 4; ++n)
                wmma::store_matrix_sync(sS + (w * 16) * APITCH + n * 16, sacc[n],
                                        APITCH, wmma::mem_row_major);
        }
        __syncthreads();

        // Softmax (2 threads per row)
        {
            const int r = tid >> 1;
            const int half = tid & 1;
            const int grow = qt * 128 + r;
            const int gc0 = j * 64 + half * 32;
            const bool diag = (j >= 2 * qt);
            const float* srow = sS + r * APITCH + half * 32;

            float mx = -3.0e38f;
#pragma unroll 8
            for (int c = 0; c < 32; ++c) {
                if (!diag || gc0 + c <= grow) {
                    float s = srow[c] * 0.125f;
                    mx = fmaxf(mx, s);
                }
            }
            mx = fmaxf(mx, __shfl_xor_sync(0xffffffffu, mx, 1));
            const float mold = sm_m[r];
            const float mnew = fmaxf(mold, mx);

            float sum = 0.0f;
            __nv_bfloat16* ph = sphi + r * APITCH + half * 32;
            __nv_bfloat16* pl = splo + r * APITCH + half * 32;
#pragma unroll 8
            for (int c = 0; c < 32; ++c) {
                float p = 0.0f;
                if (!diag || gc0 + c <= grow)
                    p = __expf(srow[c] * 0.125f - mnew);
                sum += p;
                __nv_bfloat16 hh = __float2bfloat16(p);
                ph[c] = hh;
                pl[c] = __float2bfloat16(p - __bfloat162float(hh));
            }
            sum += __shfl_xor_sync(0xffffffffu, sum, 1);
            const float corr = __expf(mold - mnew);
            if (half == 0) {
                sm_m[r] = mnew;
                sm_l[r] = sm_l[r] * corr + sum;
                sm_c[r] = corr;
            }
        }
        __syncthreads();

        // PV (warp: 16 rows x 64 dk)
        {
            wmma::fragment<wmma::accumulator, 16, 16, 16, float> oacc[4];
#pragma unroll
            for (int n = 0; n < 4; ++n) wmma::fill_fragment(oacc[n], 0.0f);
#pragma unroll
            for (int kk = 0; kk < 4; ++kk) {
                wmma::fragment<wmma::matrix_a, 16, 16, 16, __nv_bfloat16, wmma::row_major> pah, pal;
                wmma::load_matrix_sync(pah, sphi + (w * 16) * APITCH + kk * 16, APITCH);
                wmma::load_matrix_sync(pal, splo + (w * 16) * APITCH + kk * 16, APITCH);
#pragma unroll
                for (int n = 0; n < 4; ++n) {
                    wmma::fragment<wmma::matrix_b, 16, 16, 16, __nv_bfloat16, wmma::row_major> vbh, vbl;
                    wmma::load_matrix_sync(vbh, svhi + (kk * 16) * APITCH + n * 16, APITCH);
                    wmma::load_matrix_sync(vbl, svlo + (kk * 16) * APITCH + n * 16, APITCH);
                    wmma::mma_sync(oacc[n], pah, vbh, oacc[n]);
                    wmma::mma_sync(oacc[n], pah, vbl, oacc[n]);
                    wmma::mma_sync(oacc[n], pal, vbh, oacc[n]);
                }
            }
#pragma unroll
            for (int n = 0; n < 4; ++n)
                wmma::store_matrix_sync(sS + (w * 16) * APITCH + n * 16, oacc[n],
                                        APITCH, wmma::mem_row_major);
        }
        __syncthreads();

        // O = O*corr + PV (elementwise, float4)
#pragma unroll
        for (int i = 0; i < 8; ++i) {
            const int idx = tid + i * 256;
            const int row = idx >> 4;
            const int c4 = idx & 15;
            float4* Op = (float4*)(sO + row * APITCH) + c4;
            const float4 pv = *((const float4*)(sS + row * APITCH) + c4);
            const float cr = sm_c[row];
            float4 o = *Op;
            o.x = o.x * cr + pv.x;
            o.y = o.y * cr + pv.y;
            o.z = o.z * cr + pv.z;
            o.w = o.w * cr + pv.w;
            *Op = o;
        }
        __syncthreads();
    }

    // Epilogue: normalize, split to bf16 hi/lo, store
#pragma unroll
    for (int i = 0; i < 8; ++i) {
        const int idx = tid + i * 256;
        const int row = idx >> 4;
        const int c4 = idx & 15;
        const float inv = 1.0f / sm_l[row];
        float4 v = *((const float4*)(sO + row * APITCH) + c4);
        float vv[4] = {v.x * inv, v.y * inv, v.z * inv, v.w * inv};
        unsigned short hs[4], ls[4];
#pragma unroll
        for (int q = 0; q < 4; ++q) {
            __nv_bfloat16 hh = __float2bfloat16(vv[q]);
            float rr = vv[q] - __bfloat162float(hh);
            __nv_bfloat16 ll = __float2bfloat16(rr);
            hs[q] = __bfloat16_as_ushort(hh);
            ls[q] = __bfloat16_as_ushort(ll);
        }
        const size_t g = rowbase + (size_t)(qt * 128 + row) * PD + c4 * 4;
        *(uint2*)(ohi + g) = make_uint2((uint32_t)hs[0] | ((uint32_t)hs[1] << 16),
                                        (uint32_t)hs[2] | ((uint32_t)hs[3] << 16));
        *(uint2*)(olo + g) = make_uint2((uint32_t)ls[0] | ((uint32_t)ls[1] << 16),
                                        (uint32_t)ls[2] | ((uint32_t)ls[3] << 16));
    }
}

// ---------------------------------------------------------------------------
extern "C" void kernel_launch(void* const* d_in, const int* in_sizes, int n_in,
                              void* d_out, int out_size)
{
    const float* Q    = (const float*)d_in[0];
    const float* K    = (const float*)d_in[1];
    const float* V    = (const float*)d_in[2];
    const float* Wq_w = (const float*)d_in[4];
    const float* Wq_b = (const float*)d_in[5];
    const float* Wk_w = (const float*)d_in[6];
    const float* Wk_b = (const float*)d_in[7];
    const float* Wv_w = (const float*)d_in[8];
    const float* Wv_b = (const float*)d_in[9];
    const float* fc_w = (const float*)d_in[10];
    const float* fc_b = (const float*)d_in[11];
    float* out = (float*)d_out;

    __nv_bfloat16 *ihi, *ilo, *whi, *wlo, *qhi, *qlo, *khi, *klo, *vhi, *vlo, *ahi, *alo;
    cudaGetSymbolAddress((void**)&ihi, g_ihi);
    cudaGetSymbolAddress((void**)&ilo, g_ilo);
    cudaGetSymbolAddress((void**)&whi, g_whi);
    cudaGetSymbolAddress((void**)&wlo, g_wlo);
    cudaGetSymbolAddress((void**)&qhi, g_qhi);
    cudaGetSymbolAddress((void**)&qlo, g_qlo);
    cudaGetSymbolAddress((void**)&khi, g_khi);
    cudaGetSymbolAddress((void**)&klo, g_klo);
    cudaGetSymbolAddress((void**)&vhi, g_vhi);
    cudaGetSymbolAddress((void**)&vlo, g_vlo);
    cudaGetSymbolAddress((void**)&ahi, g_ahi);
    cudaGetSymbolAddress((void**)&alo, g_alo);

    cudaFuncSetAttribute(gemm3_wmma<true>,
                         cudaFuncAttributeMaxDynamicSharedMemorySize, GEMM_DSMEM);
    cudaFuncSetAttribute(gemm3_wmma<false>,
                         cudaFuncAttributeMaxDynamicSharedMemorySize, GEMM_DSMEM);
    cudaFuncSetAttribute(flash_attn_tc,
                         cudaFuncAttributeMaxDynamicSharedMemorySize, ATT_SMEM);

    const int nA4 = PM * PD / 4;
    const int nW4 = PD * PD / 4;
    dim3 ggrid(PD / GTN, PM / GTM);   // (8, 32)

    // Q projection -> qhi/qlo
    split_bf16<<<nA4 / 256, 256>>>(Q, ihi, ilo, nA4);
    split_bf16<<<nW4 / 256, 256>>>(Wq_w, whi, wlo, nW4);
    gemm3_wmma<true><<<ggrid, 256, GEMM_DSMEM>>>(ihi, ilo, whi, wlo, Wq_b,
                                                 nullptr, qhi, qlo, PD, PD);
    // K projection -> khi/klo
    split_bf16<<<nA4 / 256, 256>>>(K, ihi, ilo, nA4);
    split_bf16<<<nW4 / 256, 256>>>(Wk_w, whi, wlo, nW4);
    gemm3_wmma<true><<<ggrid, 256, GEMM_DSMEM>>>(ihi, ilo, whi, wlo, Wk_b,
                                                 nullptr, khi, klo, PD, PD);
    // V projection -> vhi/vlo
    split_bf16<<<nA4 / 256, 256>>>(V, ihi, ilo, nA4);
    split_bf16<<<nW4 / 256, 256>>>(Wv_w, whi, wlo, nW4);
    gemm3_wmma<true><<<ggrid, 256, GEMM_DSMEM>>>(ihi, ilo, whi, wlo, Wv_b,
                                                 nullptr, vhi, vlo, PD, PD);

    // Attention -> ahi/alo
    flash_attn_tc<<<dim3(PL / 128, PB * PH), 256, ATT_SMEM>>>(
        qhi, qlo, khi, klo, vhi, vlo, ahi, alo);

    // Output projection (fp32 out)
    split_bf16<<<nW4 / 256, 256>>>(fc_w, whi, wlo, nW4);
    gemm3_wmma<false><<<ggrid, 256, GEMM_DSMEM>>>(ahi, alo, whi, wlo, fc_b,
                                                  out, nullptr, nullptr, PD, PD);
}

// round 5
// speedup vs baseline: 2.0495x; 1.5699x over previous
#include <cuda_runtime.h>
#include <cuda_bf16.h>
#include <mma.h>
#include <cstdint>
#include <math.h>

using namespace nvcuda;

// Problem constants
#define PB 2
#define PL 2048
#define PD 1024
#define PH 16
#define PDK 64
#define PM (PB * PL)   // 4096

// Scratch (device globals)
__device__ __nv_bfloat16 g_ihi[PM * PD];
__device__ __nv_bfloat16 g_ilo[PM * PD];
__device__ __nv_bfloat16 g_whi[PD * PD];
__device__ __nv_bfloat16 g_wlo[PD * PD];
__device__ __nv_bfloat16 g_qhi[PM * PD];
__device__ __nv_bfloat16 g_qlo[PM * PD];
__device__ __nv_bfloat16 g_khi[PM * PD];
__device__ __nv_bfloat16 g_klo[PM * PD];
__device__ __nv_bfloat16 g_vhi[PM * PD];
__device__ __nv_bfloat16 g_vlo[PM * PD];
__device__ __nv_bfloat16 g_ahi[PM * PD];
__device__ __nv_bfloat16 g_alo[PM * PD];

// ---------------------------------------------------------------------------
// PTX helpers (baseline PTX only: sm_80-era, compiles at .target sm_103)
// ---------------------------------------------------------------------------
__device__ __forceinline__ uint32_t smem_u32(const void* p) {
    uint32_t a;
    asm("{ .reg .u64 t; cvta.to.shared.u64 t, %1; cvt.u32.u64 %0, t; }"
        : "=r"(a) : "l"(p));
    return a;
}

#define MMA16816(c, a, b) \
    asm volatile("mma.sync.aligned.m16n8k16.row.col.f32.bf16.bf16.f32 " \
        "{%0,%1,%2,%3}, {%4,%5,%6,%7}, {%8,%9}, {%0,%1,%2,%3};" \
        : "+f"((c)[0]), "+f"((c)[1]), "+f"((c)[2]), "+f"((c)[3]) \
        : "r"((a)[0]), "r"((a)[1]), "r"((a)[2]), "r"((a)[3]), \
          "r"((b)[0]), "r"((b)[1]))

#define LDSM_X4(r0, r1, r2, r3, addr) \
    asm volatile("ldmatrix.sync.aligned.m8n8.x4.shared.b16 {%0,%1,%2,%3}, [%4];" \
        : "=r"(r0), "=r"(r1), "=r"(r2), "=r"(r3) : "r"(addr))

#define LDSM_X4_T(r0, r1, r2, r3, addr) \
    asm volatile("ldmatrix.sync.aligned.m8n8.x4.trans.shared.b16 {%0,%1,%2,%3}, [%4];" \
        : "=r"(r0), "=r"(r1), "=r"(r2), "=r"(r3) : "r"(addr))

#define CP_ASYNC16(smem, gptr) \
    asm volatile("cp.async.cg.shared.global [%0], [%1], 16;" \
        :: "r"(smem), "l"(gptr))
#define CP_COMMIT() asm volatile("cp.async.commit_group;" ::: "memory")
#define CP_WAIT0()  asm volatile("cp.async.wait_group 0;" ::: "memory")

__device__ __forceinline__ float ex2f(float x) {
    float r;
    asm("ex2.approx.f32 %0, %1;" : "=f"(r) : "f"(x));
    return r;
}

// split two floats into packed bf16x2 hi and residual lo
__device__ __forceinline__ void split2(float a, float b, uint32_t& hi, uint32_t& lo) {
    __nv_bfloat16 ha = __float2bfloat16(a);
    __nv_bfloat16 hb = __float2bfloat16(b);
    float ra = a - __bfloat162float(ha);
    float rb = b - __bfloat162float(hb);
    __nv_bfloat162 H; H.x = ha; H.y = hb;
    __nv_bfloat162 L; L.x = __float2bfloat16(ra); L.y = __float2bfloat16(rb);
    hi = *reinterpret_cast<uint32_t*>(&H);
    lo = *reinterpret_cast<uint32_t*>(&L);
}

// ---------------------------------------------------------------------------
// Split fp32 -> (bf16 hi, bf16 lo)
// ---------------------------------------------------------------------------
__global__ __launch_bounds__(256) void split_bf16(
    const float* __restrict__ x,
    __nv_bfloat16* __restrict__ hi, __nv_bfloat16* __restrict__ lo, int n4)
{
    int i = blockIdx.x * 256 + threadIdx.x;
    if (i >= n4) return;
    float4 v = reinterpret_cast<const float4*>(x)[i];
    float vv[4] = {v.x, v.y, v.z, v.w};
    unsigned short hs[4], ls[4];
#pragma unroll
    for (int j = 0; j < 4; ++j) {
        __nv_bfloat16 h = __float2bfloat16(vv[j]);
        float r = vv[j] - __bfloat162float(h);
        __nv_bfloat16 l = __float2bfloat16(r);
        hs[j] = __bfloat16_as_ushort(h);
        ls[j] = __bfloat16_as_ushort(l);
    }
    reinterpret_cast<uint2*>(hi)[i] =
        make_uint2((uint32_t)hs[0] | ((uint32_t)hs[1] << 16),
                   (uint32_t)hs[2] | ((uint32_t)hs[3] << 16));
    reinterpret_cast<uint2*>(lo)[i] =
        make_uint2((uint32_t)ls[0] | ((uint32_t)ls[1] << 16),
                   (uint32_t)ls[2] | ((uint32_t)ls[3] << 16));
}

// ---------------------------------------------------------------------------
// wmma bf16 GEMM (3-term split) — unchanged from round 4.
// ---------------------------------------------------------------------------
#define GTM 128
#define GTN 128
#define GTK 32
#define SPITCH 40
#define TILE_B (128 * SPITCH * 2)
#define STAGE_B (4 * TILE_B)
#define GEMM_DSMEM (2 * STAGE_B)

template <bool SPLIT>
__global__ __launch_bounds__(256, 1) void gemm3_wmma(
    const __nv_bfloat16* __restrict__ Ahi, const __nv_bfloat16* __restrict__ Alo,
    const __nv_bfloat16* __restrict__ Bhi, const __nv_bfloat16* __restrict__ Blo,
    const float* __restrict__ bias, float* __restrict__ C,
    __nv_bfloat16* __restrict__ Chi, __nv_bfloat16* __restrict__ Clo,
    int K, int N)
{
    extern __shared__ char dsm[];
    __shared__ float sbias[GTN];

    const int tid = threadIdx.x;
    const int wid = tid >> 5;
    const int lane = tid & 31;
    const int wm = wid & 3;
    const int wn = wid >> 2;
    const int bm = blockIdx.y * GTM;
    const int bn = blockIdx.x * GTN;

    if (tid < GTN) sbias[tid] = bias[bn + tid];

    wmma::fragment<wmma::accumulator, 16, 16, 16, float> acc[2][4];
#pragma unroll
    for (int i = 0; i < 2; ++i)
#pragma unroll
        for (int j = 0; j < 4; ++j) wmma::fill_fragment(acc[i][j], 0.0f);

    auto sAhi = [&](int s) { return (__nv_bfloat16*)(dsm + s * STAGE_B); };
    auto sAlo = [&](int s) { return (__nv_bfloat16*)(dsm + s * STAGE_B + TILE_B); };
    auto sBhi = [&](int s) { return (__nv_bfloat16*)(dsm + s * STAGE_B + 2 * TILE_B); };
    auto sBlo = [&](int s) { return (__nv_bfloat16*)(dsm + s * STAGE_B + 3 * TILE_B); };

    const int r0 = tid >> 2;
    const int c0 = (tid & 3) * 8;

#pragma unroll
    for (int it = 0; it < 2; ++it) {
        const int r = r0 + it * 64;
        const size_t goA = (size_t)(bm + r) * K + c0;
        const size_t goB = (size_t)(bn + r) * K + c0;
        *(uint4*)(sAhi(0) + r * SPITCH + c0) = *(const uint4*)(Ahi + goA);
        *(uint4*)(sAlo(0) + r * SPITCH + c0) = *(const uint4*)(Alo + goA);
        *(uint4*)(sBhi(0) + r * SPITCH + c0) = *(const uint4*)(Bhi + goB);
        *(uint4*)(sBlo(0) + r * SPITCH + c0) = *(const uint4*)(Blo + goB);
    }
    __syncthreads();

    const int nchunk = K / GTK;
    for (int c = 0; c < nchunk; ++c) {
        const int s = c & 1;
        uint4 stg[8];
        if (c + 1 < nchunk) {
            const int k1 = (c + 1) * GTK;
#pragma unroll
            for (int it = 0; it < 2; ++it) {
                const int r = r0 + it * 64;
                const size_t goA = (size_t)(bm + r) * K + k1 + c0;
                const size_t goB = (size_t)(bn + r) * K + k1 + c0;
                stg[it * 4 + 0] = *(const uint4*)(Ahi + goA);
                stg[it * 4 + 1] = *(const uint4*)(Alo + goA);
                stg[it * 4 + 2] = *(const uint4*)(Bhi + goB);
                stg[it * 4 + 3] = *(const uint4*)(Blo + goB);
            }
        }

        const __nv_bfloat16* pAhi = sAhi(s) + wm * 32 * SPITCH;
        const __nv_bfloat16* pAlo = sAlo(s) + wm * 32 * SPITCH;
        const __nv_bfloat16* pBhi = sBhi(s) + wn * 64 * SPITCH;
        const __nv_bfloat16* pBlo = sBlo(s) + wn * 64 * SPITCH;
#pragma unroll
        for (int kk = 0; kk < 2; ++kk) {
            wmma::fragment<wmma::matrix_a, 16, 16, 16, __nv_bfloat16, wmma::row_major> fahi[2], falo[2];
#pragma unroll
            for (int i = 0; i < 2; ++i) {
                wmma::load_matrix_sync(fahi[i], pAhi + i * 16 * SPITCH + kk * 16, SPITCH);
                wmma::load_matrix_sync(falo[i], pAlo + i * 16 * SPITCH + kk * 16, SPITCH);
            }
#pragma unroll
            for (int j = 0; j < 4; ++j) {
                wmma::fragment<wmma::matrix_b, 16, 16, 16, __nv_bfloat16, wmma::col_major> fbhi, fblo;
                wmma::load_matrix_sync(fbhi, pBhi + j * 16 * SPITCH + kk * 16, SPITCH);
                wmma::load_matrix_sync(fblo, pBlo + j * 16 * SPITCH + kk * 16, SPITCH);
#pragma unroll
                for (int i = 0; i < 2; ++i) {
                    wmma::mma_sync(acc[i][j], fahi[i], fbhi, acc[i][j]);
                    wmma::mma_sync(acc[i][j], fahi[i], fblo, acc[i][j]);
                    wmma::mma_sync(acc[i][j], falo[i], fbhi, acc[i][j]);
                }
            }
        }

        if (c + 1 < nchunk) {
            const int s1 = 1 - s;
#pragma unroll
            for (int it = 0; it < 2; ++it) {
                const int r = r0 + it * 64;
                *(uint4*)(sAhi(s1) + r * SPITCH + c0) = stg[it * 4 + 0];
                *(uint4*)(sAlo(s1) + r * SPITCH + c0) = stg[it * 4 + 1];
                *(uint4*)(sBhi(s1) + r * SPITCH + c0) = stg[it * 4 + 2];
                *(uint4*)(sBlo(s1) + r * SPITCH + c0) = stg[it * 4 + 3];
            }
        }
        __syncthreads();
    }

    float* ws = (float*)dsm + wid * (32 * 64);
#pragma unroll
    for (int i = 0; i < 2; ++i)
#pragma unroll
        for (int j = 0; j < 4; ++j)
            wmma::store_matrix_sync(ws + i * 16 * 64 + j * 16, acc[i][j], 64,
                                    wmma::mem_row_major);
    __syncwarp();

    const int m = bm + wm * 32 + lane;
    const size_t obase = (size_t)m * N + bn + wn * 64;
    const float* wrow = ws + lane * 64;
    const float* brow = sbias + wn * 64;
#pragma unroll
    for (int cc = 0; cc < 16; ++cc) {
        float4 v = *(const float4*)(wrow + cc * 4);
        v.x += brow[cc * 4 + 0];
        v.y += brow[cc * 4 + 1];
        v.z += brow[cc * 4 + 2];
        v.w += brow[cc * 4 + 3];
        if (SPLIT) {
            float vv[4] = {v.x, v.y, v.z, v.w};
            unsigned short hs[4], ls[4];
#pragma unroll
            for (int q = 0; q < 4; ++q) {
                __nv_bfloat16 h = __float2bfloat16(vv[q]);
                float r = vv[q] - __bfloat162float(h);
                __nv_bfloat16 l = __float2bfloat16(r);
                hs[q] = __bfloat16_as_ushort(h);
                ls[q] = __bfloat16_as_ushort(l);
            }
            *(uint2*)(Chi + obase + cc * 4) =
                make_uint2((uint32_t)hs[0] | ((uint32_t)hs[1] << 16),
                           (uint32_t)hs[2] | ((uint32_t)hs[3] << 16));
            *(uint2*)(Clo + obase + cc * 4) =
                make_uint2((uint32_t)ls[0] | ((uint32_t)ls[1] << 16),
                           (uint32_t)ls[2] | ((uint32_t)ls[3] << 16));
        } else {
            *(float4*)(C + obase + cc * 4) = v;
        }
    }
}

// ---------------------------------------------------------------------------
// Register-resident FA2 on mma.sync, bf16 3-term split, DK=64.
// grid = (16, 32), 256 threads (8 warps x 16 rows), KV tiles of 64,
// cp.async double-buffered KV, O/S in registers, P relayout C->A in regs.
// ---------------------------------------------------------------------------
#define FPITCH 72                       // bf16 pitch (144B: conflict-free ldsm)
#define AQ_HI 0
#define AQ_LO 18432
#define AKV   36864
#define KV_STAGE 36864
#define AK_HI 0
#define AK_LO 9216
#define AV_HI 18432
#define AV_LO 27648
#define ATT_SMEM (AKV + 2 * KV_STAGE)   // 110592

#define SFC 0.18033688f                 // 0.125 * log2(e)

__global__ __launch_bounds__(256, 1) void flash_attn_mma(
    const __nv_bfloat16* __restrict__ qhi, const __nv_bfloat16* __restrict__ qlo,
    const __nv_bfloat16* __restrict__ khi, const __nv_bfloat16* __restrict__ klo,
    const __nv_bfloat16* __restrict__ vhi, const __nv_bfloat16* __restrict__ vlo,
    __nv_bfloat16* __restrict__ ohi, __nv_bfloat16* __restrict__ olo)
{
    extern __shared__ char dsm[];
    const int tid = threadIdx.x;
    const int w = tid >> 5;
    const int lane = tid & 31;
    const int g = lane >> 2;
    const int tq = lane & 3;
    const int qt = (int)(gridDim.x - 1) - (int)blockIdx.x;   // heavy CTAs first
    const int b = blockIdx.y >> 4;
    const int h = blockIdx.y & 15;
    const size_t rowbase = (size_t)b * PL * PD + (size_t)h * PDK;

    const uint32_t sQh = smem_u32(dsm + AQ_HI);
    const uint32_t sQl = smem_u32(dsm + AQ_LO);
    const uint32_t sKV = smem_u32(dsm + AKV);

    // per-thread KV load mapping (2 its x 16B per array)
    const int kr0 = tid >> 3;              // 0..31 (+32)
    const int kc0 = (tid & 7) * 8;         // 0..56

    // ---- prologue: issue cp.async for tile 0 into buffer 0 ----
    {
        const uint32_t sb = sKV;
#pragma unroll
        for (int it = 0; it < 2; ++it) {
            const int r = kr0 + it * 32;
            const uint32_t so = (uint32_t)(r * FPITCH + kc0) * 2;
            const size_t go = rowbase + (size_t)r * PD + kc0;   // tile j=0
            CP_ASYNC16(sb + AK_HI + so, (const char*)(khi + go));
            CP_ASYNC16(sb + AK_LO + so, (const char*)(klo + go));
            CP_ASYNC16(sb + AV_HI + so, (const char*)(vhi + go));
            CP_ASYNC16(sb + AV_LO + so, (const char*)(vlo + go));
        }
        CP_COMMIT();
    }

    // ---- load Q tile to smem (LDG/STS) ----
#pragma unroll
    for (int it = 0; it < 4; ++it) {
        const int idx = tid + it * 256;
        const int r = idx >> 3;
        const int c = (idx & 7) * 8;
        const size_t go = rowbase + (size_t)(qt * 128 + r) * PD + c;
        const uint32_t so = (uint32_t)(r * FPITCH + c) * 2;
        *(uint4*)(dsm + AQ_HI + so) = *(const uint4*)(qhi + go);
        *(uint4*)(dsm + AQ_LO + so) = *(const uint4*)(qlo + go);
    }
    CP_WAIT0();
    __syncthreads();

    // ---- Q fragments (ldmatrix x4, per warp: rows w*16..w*16+15) ----
    uint32_t qh[4][4], ql[4][4];
    {
        const int row = w * 16 + (lane & 7) + ((lane >> 3) & 1) * 8;
#pragma unroll
        for (int kb = 0; kb < 4; ++kb) {
            const int col = kb * 16 + ((lane >> 4) & 1) * 8;
            const uint32_t off = (uint32_t)(row * FPITCH + col) * 2;
            LDSM_X4(qh[kb][0], qh[kb][1], qh[kb][2], qh[kb][3], sQh + off);
            LDSM_X4(ql[kb][0], ql[kb][1], ql[kb][2], ql[kb][3], sQl + off);
        }
    }

    float oacc[8][4];
#pragma unroll
    for (int nb = 0; nb < 8; ++nb)
#pragma unroll
        for (int e = 0; e < 4; ++e) oacc[nb][e] = 0.0f;
    float m0 = -1.0e30f, m1 = -1.0e30f, l0 = 0.0f, l1 = 0.0f;

    const int jmax = 2 * qt + 1;
    for (int j = 0; j <= jmax; ++j) {
        const int buf = j & 1;
        const uint32_t sb = sKV + buf * KV_STAGE;

        // prefetch next KV tile into other buffer
        if (j < jmax) {
            const uint32_t nb_ = sKV + (buf ^ 1) * KV_STAGE;
#pragma unroll
            for (int it = 0; it < 2; ++it) {
                const int r = kr0 + it * 32;
                const uint32_t so = (uint32_t)(r * FPITCH + kc0) * 2;
                const size_t go = rowbase + (size_t)((j + 1) * 64 + r) * PD + kc0;
                CP_ASYNC16(nb_ + AK_HI + so, (const char*)(khi + go));
                CP_ASYNC16(nb_ + AK_LO + so, (const char*)(klo + go));
                CP_ASYNC16(nb_ + AV_HI + so, (const char*)(vhi + go));
                CP_ASYNC16(nb_ + AV_LO + so, (const char*)(vlo + go));
            }
            CP_COMMIT();
        }

        // ---- S = Q K^T (3-term), register accumulators ----
        float sacc[8][4];
#pragma unroll
        for (int nb = 0; nb < 8; ++nb)
#pragma unroll
            for (int e = 0; e < 4; ++e) sacc[nb][e] = 0.0f;

#pragma unroll
        for (int kb = 0; kb < 4; ++kb) {
            uint32_t kh[8][2], kl[8][2];
            const int kcol = kb * 16 + ((lane >> 3) & 1) * 8;
#pragma unroll
            for (int np = 0; np < 4; ++np) {
                const int krow = np * 16 + (lane & 7) + ((lane >> 4) & 1) * 8;
                const uint32_t off = (uint32_t)(krow * FPITCH + kcol) * 2;
                LDSM_X4(kh[2 * np][0], kh[2 * np][1], kh[2 * np + 1][0], kh[2 * np + 1][1],
                        sb + AK_HI + off);
                LDSM_X4(kl[2 * np][0], kl[2 * np][1], kl[2 * np + 1][0], kl[2 * np + 1][1],
                        sb + AK_LO + off);
            }
#pragma unroll
            for (int nb = 0; nb < 8; ++nb) {
                MMA16816(sacc[nb], qh[kb], kh[nb]);
                MMA16816(sacc[nb], qh[kb], kl[nb]);
                MMA16816(sacc[nb], ql[kb], kh[nb]);
            }
        }

        // ---- causal mask (only possible on last two tiles) ----
        if (j >= 2 * qt) {
            const int row0 = qt * 128 + w * 16 + g;
            const int row1 = row0 + 8;
            const int cb = j * 64 + 2 * tq;
#pragma unroll
            for (int nb = 0; nb < 8; ++nb) {
                const int c0 = cb + nb * 8, c1 = c0 + 1;
                if (c0 > row0) sacc[nb][0] = -1.0e30f;
                if (c1 > row0) sacc[nb][1] = -1.0e30f;
                if (c0 > row1) sacc[nb][2] = -1.0e30f;
                if (c1 > row1) sacc[nb][3] = -1.0e30f;
            }
        }

        // ---- online softmax in registers (rows g, g+8) ----
        float mx0 = -1.0e30f, mx1 = -1.0e30f;
#pragma unroll
        for (int nb = 0; nb < 8; ++nb) {
            mx0 = fmaxf(mx0, fmaxf(sacc[nb][0], sacc[nb][1]));
            mx1 = fmaxf(mx1, fmaxf(sacc[nb][2], sacc[nb][3]));
        }
        mx0 = fmaxf(mx0, __shfl_xor_sync(0xffffffffu, mx0, 1));
        mx0 = fmaxf(mx0, __shfl_xor_sync(0xffffffffu, mx0, 2));
        mx1 = fmaxf(mx1, __shfl_xor_sync(0xffffffffu, mx1, 1));
        mx1 = fmaxf(mx1, __shfl_xor_sync(0xffffffffu, mx1, 2));

        const float mn0 = fmaxf(m0, mx0);
        const float mn1 = fmaxf(m1, mx1);
        const float em0 = mn0 * SFC;
        const float em1 = mn1 * SFC;
        const float cr0 = ex2f((m0 - mn0) * SFC);
        const float cr1 = ex2f((m1 - mn1) * SFC);
        m0 = mn0; m1 = mn1;

        float s0 = 0.0f, s1 = 0.0f;
#pragma unroll
        for (int nb = 0; nb < 8; ++nb) {
            float p0 = ex2f(fmaf(sacc[nb][0], SFC, -em0));
            float p1 = ex2f(fmaf(sacc[nb][1], SFC, -em0));
            float p2 = ex2f(fmaf(sacc[nb][2], SFC, -em1));
            float p3 = ex2f(fmaf(sacc[nb][3], SFC, -em1));
            sacc[nb][0] = p0; sacc[nb][1] = p1;
            sacc[nb][2] = p2; sacc[nb][3] = p3;
            s0 += p0 + p1; s1 += p2 + p3;
        }
        s0 += __shfl_xor_sync(0xffffffffu, s0, 1);
        s0 += __shfl_xor_sync(0xffffffffu, s0, 2);
        s1 += __shfl_xor_sync(0xffffffffu, s1, 1);
        s1 += __shfl_xor_sync(0xffffffffu, s1, 2);
        l0 = l0 * cr0 + s0;
        l1 = l1 * cr1 + s1;

#pragma unroll
        for (int nb = 0; nb < 8; ++nb) {
            oacc[nb][0] *= cr0; oacc[nb][1] *= cr0;
            oacc[nb][2] *= cr1; oacc[nb][3] *= cr1;
        }

        // ---- P: C-fragment -> A-fragment relayout (registers only) ----
        uint32_t pa[4][4], pl[4][4];
#pragma unroll
        for (int kb = 0; kb < 4; ++kb) {
            split2(sacc[2 * kb][0], sacc[2 * kb][1], pa[kb][0], pl[kb][0]);
            split2(sacc[2 * kb][2], sacc[2 * kb][3], pa[kb][1], pl[kb][1]);
            split2(sacc[2 * kb + 1][0], sacc[2 * kb + 1][1], pa[kb][2], pl[kb][2]);
            split2(sacc[2 * kb + 1][2], sacc[2 * kb + 1][3], pa[kb][3], pl[kb][3]);
        }

        // ---- O += P V (3-term), V via ldmatrix.trans ----
#pragma unroll
        for (int kb = 0; kb < 4; ++kb) {
            uint32_t vh[8][2], vl[8][2];
            const int vrow = kb * 16 + (lane & 7) + ((lane >> 3) & 1) * 8;
#pragma unroll
            for (int np = 0; np < 4; ++np) {
                const int vcol = np * 16 + ((lane >> 4) & 1) * 8;
                const uint32_t off = (uint32_t)(vrow * FPITCH + vcol) * 2;
                LDSM_X4_T(vh[2 * np][0], vh[2 * np][1], vh[2 * np + 1][0], vh[2 * np + 1][1],
                          sb + AV_HI + off);
                LDSM_X4_T(vl[2 * np][0], vl[2 * np][1], vl[2 * np + 1][0], vl[2 * np + 1][1],
                          sb + AV_LO + off);
            }
#pragma unroll
            for (int nb = 0; nb < 8; ++nb) {
                MMA16816(oacc[nb], pa[kb], vh[nb]);
                MMA16816(oacc[nb], pa[kb], vl[nb]);
                MMA16816(oacc[nb], pl[kb], vh[nb]);
            }
        }

        if (j < jmax) {
            CP_WAIT0();
            __syncthreads();
        }
    }

    // ---- epilogue: normalize, split hi/lo, store ----
    const float inv0 = 1.0f / l0;
    const float inv1 = 1.0f / l1;
    const int row0 = qt * 128 + w * 16 + g;
#pragma unroll
    for (int nb = 0; nb < 8; ++nb) {
        const int col = nb * 8 + 2 * tq;
        uint32_t hi, lo;
        split2(oacc[nb][0] * inv0, oacc[nb][1] * inv0, hi, lo);
        const size_t g0 = rowbase + (size_t)row0 * PD + col;
        *(uint32_t*)(ohi + g0) = hi;
        *(uint32_t*)(olo + g0) = lo;
        split2(oacc[nb][2] * inv1, oacc[nb][3] * inv1, hi, lo);
        const size_t g1 = rowbase + (size_t)(row0 + 8) * PD + col;
        *(uint32_t*)(ohi + g1) = hi;
        *(uint32_t*)(olo + g1) = lo;
    }
}

// ---------------------------------------------------------------------------
extern "C" void kernel_launch(void* const* d_in, const int* in_sizes, int n_in,
                              void* d_out, int out_size)
{
    const float* Q    = (const float*)d_in[0];
    const float* K    = (const float*)d_in[1];
    const float* V    = (const float*)d_in[2];
    const float* Wq_w = (const float*)d_in[4];
    const float* Wq_b = (const float*)d_in[5];
    const float* Wk_w = (const float*)d_in[6];
    const float* Wk_b = (const float*)d_in[7];
    const float* Wv_w = (const float*)d_in[8];
    const float* Wv_b = (const float*)d_in[9];
    const float* fc_w = (const float*)d_in[10];
    const float* fc_b = (const float*)d_in[11];
    float* out = (float*)d_out;

    __nv_bfloat16 *ihi, *ilo, *whi, *wlo, *qhi, *qlo, *khi, *klo, *vhi, *vlo, *ahi, *alo;
    cudaGetSymbolAddress((void**)&ihi, g_ihi);
    cudaGetSymbolAddress((void**)&ilo, g_ilo);
    cudaGetSymbolAddress((void**)&whi, g_whi);
    cudaGetSymbolAddress((void**)&wlo, g_wlo);
    cudaGetSymbolAddress((void**)&qhi, g_qhi);
    cudaGetSymbolAddress((void**)&qlo, g_qlo);
    cudaGetSymbolAddress((void**)&khi, g_khi);
    cudaGetSymbolAddress((void**)&klo, g_klo);
    cudaGetSymbolAddress((void**)&vhi, g_vhi);
    cudaGetSymbolAddress((void**)&vlo, g_vlo);
    cudaGetSymbolAddress((void**)&ahi, g_ahi);
    cudaGetSymbolAddress((void**)&alo, g_alo);

    cudaFuncSetAttribute(gemm3_wmma<true>,
                         cudaFuncAttributeMaxDynamicSharedMemorySize, GEMM_DSMEM);
    cudaFuncSetAttribute(gemm3_wmma<false>,
                         cudaFuncAttributeMaxDynamicSharedMemorySize, GEMM_DSMEM);
    cudaFuncSetAttribute(flash_attn_mma,
                         cudaFuncAttributeMaxDynamicSharedMemorySize, ATT_SMEM);

    const int nA4 = PM * PD / 4;
    const int nW4 = PD * PD / 4;
    dim3 ggrid(PD / GTN, PM / GTM);   // (8, 32)

    // Q projection -> qhi/qlo
    split_bf16<<<nA4 / 256, 256>>>(Q, ihi, ilo, nA4);
    split_bf16<<<nW4 / 256, 256>>>(Wq_w, whi, wlo, nW4);
    gemm3_wmma<true><<<ggrid, 256, GEMM_DSMEM>>>(ihi, ilo, whi, wlo, Wq_b,
                                                 nullptr, qhi, qlo, PD, PD);
    // K projection -> khi/klo
    split_bf16<<<nA4 / 256, 256>>>(K, ihi, ilo, nA4);
    split_bf16<<<nW4 / 256, 256>>>(Wk_w, whi, wlo, nW4);
    gemm3_wmma<true><<<ggrid, 256, GEMM_DSMEM>>>(ihi, ilo, whi, wlo, Wk_b,
                                                 nullptr, khi, klo, PD, PD);
    // V projection -> vhi/vlo
    split_bf16<<<nA4 / 256, 256>>>(V, ihi, ilo, nA4);
    split_bf16<<<nW4 / 256, 256>>>(Wv_w, whi, wlo, nW4);
    gemm3_wmma<true><<<ggrid, 256, GEMM_DSMEM>>>(ihi, ilo, whi, wlo, Wv_b,
                                                 nullptr, vhi, vlo, PD, PD);

    // Attention -> ahi/alo (register-resident FA2)
    flash_attn_mma<<<dim3(PL / 128, PB * PH), 256, ATT_SMEM>>>(
        qhi, qlo, khi, klo, vhi, vlo, ahi, alo);

    // Output projection (fp32 out)
    split_bf16<<<nW4 / 256, 256>>>(fc_w, whi, wlo, nW4);
    gemm3_wmma<false><<<ggrid, 256, GEMM_DSMEM>>>(ahi, alo, whi, wlo, fc_b,
                                                  out, nullptr, nullptr, PD, PD);
}

// round 6
// speedup vs baseline: 2.7763x; 1.3546x over previous
#include <cuda_runtime.h>
#include <cuda_bf16.h>
#include <cstdint>
#include <math.h>

// Problem constants
#define PB 2
#define PL 2048
#define PD 1024
#define PH 16
#define PDK 64
#define PM (PB * PL)   // 4096

// Scratch (device globals)
__device__ __nv_bfloat16 g_ihi[PM * PD];
__device__ __nv_bfloat16 g_ilo[PM * PD];
__device__ __nv_bfloat16 g_whi[PD * PD];
__device__ __nv_bfloat16 g_wlo[PD * PD];
__device__ __nv_bfloat16 g_qhi[PM * PD];
__device__ __nv_bfloat16 g_qlo[PM * PD];
__device__ __nv_bfloat16 g_khi[PM * PD];
__device__ __nv_bfloat16 g_klo[PM * PD];
__device__ __nv_bfloat16 g_vhi[PM * PD];
__device__ __nv_bfloat16 g_vlo[PM * PD];
__device__ __nv_bfloat16 g_ahi[PM * PD];
__device__ __nv_bfloat16 g_alo[PM * PD];

// ---------------------------------------------------------------------------
// PTX helpers (baseline PTX only)
// ---------------------------------------------------------------------------
__device__ __forceinline__ uint32_t smem_u32(const void* p) {
    uint32_t a;
    asm("{ .reg .u64 t; cvta.to.shared.u64 t, %1; cvt.u32.u64 %0, t; }"
        : "=r"(a) : "l"(p));
    return a;
}

#define MMA16816(c, a, b) \
    asm volatile("mma.sync.aligned.m16n8k16.row.col.f32.bf16.bf16.f32 " \
        "{%0,%1,%2,%3}, {%4,%5,%6,%7}, {%8,%9}, {%0,%1,%2,%3};" \
        : "+f"((c)[0]), "+f"((c)[1]), "+f"((c)[2]), "+f"((c)[3]) \
        : "r"((a)[0]), "r"((a)[1]), "r"((a)[2]), "r"((a)[3]), \
          "r"((b)[0]), "r"((b)[1]))

#define LDSM_X4(r0, r1, r2, r3, addr) \
    asm volatile("ldmatrix.sync.aligned.m8n8.x4.shared.b16 {%0,%1,%2,%3}, [%4];" \
        : "=r"(r0), "=r"(r1), "=r"(r2), "=r"(r3) : "r"(addr))

#define LDSM_X4_T(r0, r1, r2, r3, addr) \
    asm volatile("ldmatrix.sync.aligned.m8n8.x4.trans.shared.b16 {%0,%1,%2,%3}, [%4];" \
        : "=r"(r0), "=r"(r1), "=r"(r2), "=r"(r3) : "r"(addr))

#define CP_ASYNC16(smem, gptr) \
    asm volatile("cp.async.cg.shared.global [%0], [%1], 16;" \
        :: "r"(smem), "l"(gptr))
#define CP_COMMIT() asm volatile("cp.async.commit_group;" ::: "memory")
#define CP_WAIT0()  asm volatile("cp.async.wait_group 0;" ::: "memory")
#define CP_WAIT1()  asm volatile("cp.async.wait_group 1;" ::: "memory")

__device__ __forceinline__ float ex2f(float x) {
    float r;
    asm("ex2.approx.f32 %0, %1;" : "=f"(r) : "f"(x));
    return r;
}

__device__ __forceinline__ void split2(float a, float b, uint32_t& hi, uint32_t& lo) {
    __nv_bfloat16 ha = __float2bfloat16(a);
    __nv_bfloat16 hb = __float2bfloat16(b);
    float ra = a - __bfloat162float(ha);
    float rb = b - __bfloat162float(hb);
    __nv_bfloat162 H; H.x = ha; H.y = hb;
    __nv_bfloat162 L; L.x = __float2bfloat16(ra); L.y = __float2bfloat16(rb);
    hi = *reinterpret_cast<uint32_t*>(&H);
    lo = *reinterpret_cast<uint32_t*>(&L);
}

// ---------------------------------------------------------------------------
// Split fp32 -> (bf16 hi, bf16 lo)
// ---------------------------------------------------------------------------
__global__ __launch_bounds__(256) void split_bf16(
    const float* __restrict__ x,
    __nv_bfloat16* __restrict__ hi, __nv_bfloat16* __restrict__ lo, int n4)
{
    int i = blockIdx.x * 256 + threadIdx.x;
    if (i >= n4) return;
    float4 v = reinterpret_cast<const float4*>(x)[i];
    uint32_t h0, l0, h1, l1;
    split2(v.x, v.y, h0, l0);
    split2(v.z, v.w, h1, l1);
    reinterpret_cast<uint2*>(hi)[i] = make_uint2(h0, h1);
    reinterpret_cast<uint2*>(lo)[i] = make_uint2(l0, l1);
}

// ---------------------------------------------------------------------------
// mma.sync bf16 GEMM (3-term split): C[m,n] = sum_k A[m,k]*B[n,k] + bias[n]
// 128x256x32 tiles, 8 warps (2m x 4n), warp tile 64x64.
// cp.async 3-stage pipeline; register-resident accumulators; direct epilogue.
// ---------------------------------------------------------------------------
#define BGM 128
#define BGN 256
#define BGK 32
#define GP 40                             // smem pitch (bf16)
#define A_T (BGM * GP * 2)                // 10240 B
#define B_T (BGN * GP * 2)                // 20480 B
#define OFF_GA_HI 0
#define OFF_GA_LO A_T
#define OFF_GB_HI (2 * A_T)
#define OFF_GB_LO (2 * A_T + B_T)
#define STG_B (2 * A_T + 2 * B_T)         // 61440 B
#define NST 3
#define G_SMEM (NST * STG_B)              // 184320 B

template <bool SPLIT>
__global__ __launch_bounds__(256, 1) void gemm3_mma(
    const __nv_bfloat16* __restrict__ Ahi, const __nv_bfloat16* __restrict__ Alo,
    const __nv_bfloat16* __restrict__ Bhi, const __nv_bfloat16* __restrict__ Blo,
    const float* __restrict__ bias, float* __restrict__ C,
    __nv_bfloat16* __restrict__ Chi, __nv_bfloat16* __restrict__ Clo,
    int K, int N)
{
    extern __shared__ char dsm[];
    __shared__ float sbias[BGN];

    const int tid = threadIdx.x;
    const int w = tid >> 5;
    const int lane = tid & 31;
    const int wm = w >> 2;          // 0..1
    const int wn = w & 3;           // 0..3
    const int g = lane >> 2;
    const int tq = lane & 3;
    const int bm = blockIdx.y * BGM;
    const int bn = blockIdx.x * BGN;
    const uint32_t sbase = smem_u32(dsm);

    // cp.async load mapping
    const int lr = tid >> 2;              // 0..63
    const int lc = (tid & 3) * 8;         // element col of 16B chunk

    auto issue = [&](int c, int buf) {
        const uint32_t sb = sbase + buf * STG_B;
        const int kofs = c * BGK;
#pragma unroll
        for (int it = 0; it < 2; ++it) {
            const int r = lr + it * 64;
            const uint32_t so = (uint32_t)(r * GP + lc) * 2;
            const size_t go = (size_t)(bm + r) * K + kofs + lc;
            CP_ASYNC16(sb + OFF_GA_HI + so, (const char*)(Ahi + go));
            CP_ASYNC16(sb + OFF_GA_LO + so, (const char*)(Alo + go));
        }
#pragma unroll
        for (int it = 0; it < 4; ++it) {
            const int r = lr + it * 64;
            const uint32_t so = (uint32_t)(r * GP + lc) * 2;
            const size_t go = (size_t)(bn + r) * K + kofs + lc;
            CP_ASYNC16(sb + OFF_GB_HI + so, (const char*)(Bhi + go));
            CP_ASYNC16(sb + OFF_GB_LO + so, (const char*)(Blo + go));
        }
    };

    // prologue: stages 0 and 1
    issue(0, 0); CP_COMMIT();
    issue(1, 1); CP_COMMIT();

    sbias[tid] = bias[bn + tid];   // blockDim == BGN == 256

    float acc[4][8][4];
#pragma unroll
    for (int mi = 0; mi < 4; ++mi)
#pragma unroll
        for (int nb = 0; nb < 8; ++nb)
#pragma unroll
            for (int e = 0; e < 4; ++e) acc[mi][nb][e] = 0.0f;

    // ldmatrix lane addressing (A-operand: row bit3, col bit4; B: row bit4, col bit3)
    const int a_r = (lane & 7) + ((lane >> 3) & 1) * 8;
    const int a_c = ((lane >> 4) & 1) * 8;
    const int b_r = (lane & 7) + ((lane >> 4) & 1) * 8;
    const int b_c = ((lane >> 3) & 1) * 8;

    const int nchunk = K / BGK;   // 32
    for (int c = 0; c < nchunk; ++c) {
        if (c + 1 < nchunk) CP_WAIT1(); else CP_WAIT0();
        __syncthreads();
        if (c + 2 < nchunk) { issue(c + 2, (c + 2) % NST); CP_COMMIT(); }

        const uint32_t sb = sbase + (c % NST) * STG_B;
#pragma unroll
        for (int kk = 0; kk < 2; ++kk) {
            uint32_t ah[4][4], al[4][4];
#pragma unroll
            for (int mi = 0; mi < 4; ++mi) {
                const uint32_t off =
                    (uint32_t)((wm * 64 + mi * 16 + a_r) * GP + kk * 16 + a_c) * 2;
                LDSM_X4(ah[mi][0], ah[mi][1], ah[mi][2], ah[mi][3],
                        sb + OFF_GA_HI + off);
                LDSM_X4(al[mi][0], al[mi][1], al[mi][2], al[mi][3],
                        sb + OFF_GA_LO + off);
            }
            uint32_t bh[8][2], bl[8][2];
#pragma unroll
            for (int np = 0; np < 4; ++np) {
                const uint32_t off =
                    (uint32_t)((wn * 64 + np * 16 + b_r) * GP + kk * 16 + b_c) * 2;
                LDSM_X4(bh[2 * np][0], bh[2 * np][1], bh[2 * np + 1][0], bh[2 * np + 1][1],
                        sb + OFF_GB_HI + off);
                LDSM_X4(bl[2 * np][0], bl[2 * np][1], bl[2 * np + 1][0], bl[2 * np + 1][1],
                        sb + OFF_GB_LO + off);
            }
#pragma unroll
            for (int mi = 0; mi < 4; ++mi)
#pragma unroll
                for (int nb = 0; nb < 8; ++nb) {
                    MMA16816(acc[mi][nb], ah[mi], bh[nb]);
                    MMA16816(acc[mi][nb], ah[mi], bl[nb]);
                    MMA16816(acc[mi][nb], al[mi], bh[nb]);
                }
        }
    }

    // epilogue: bias add + direct store from registers
#pragma unroll
    for (int mi = 0; mi < 4; ++mi) {
        const int row0 = bm + wm * 64 + mi * 16 + g;
        const int row1 = row0 + 8;
#pragma unroll
        for (int nb = 0; nb < 8; ++nb) {
            const int coll = wn * 64 + nb * 8 + 2 * tq;     // local col
            const float b0 = sbias[coll];
            const float b1 = sbias[coll + 1];
            const float v0 = acc[mi][nb][0] + b0;
            const float v1 = acc[mi][nb][1] + b1;
            const float v2 = acc[mi][nb][2] + b0;
            const float v3 = acc[mi][nb][3] + b1;
            const size_t o0 = (size_t)row0 * N + bn + coll;
            const size_t o1 = (size_t)row1 * N + bn + coll;
            if (SPLIT) {
                uint32_t hi, lo;
                split2(v0, v1, hi, lo);
                *(uint32_t*)(Chi + o0) = hi;
                *(uint32_t*)(Clo + o0) = lo;
                split2(v2, v3, hi, lo);
                *(uint32_t*)(Chi + o1) = hi;
                *(uint32_t*)(Clo + o1) = lo;
            } else {
                *(float2*)(C + o0) = make_float2(v0, v1);
                *(float2*)(C + o1) = make_float2(v2, v3);
            }
        }
    }
}

// ---------------------------------------------------------------------------
// Register-resident FA2 on mma.sync (unchanged from round 5).
// ---------------------------------------------------------------------------
#define FPITCH 72
#define AQ_HI 0
#define AQ_LO 18432
#define AKV   36864
#define KV_STAGE 36864
#define AK_HI 0
#define AK_LO 9216
#define AV_HI 18432
#define AV_LO 27648
#define ATT_SMEM (AKV + 2 * KV_STAGE)

#define SFC 0.18033688f

__global__ __launch_bounds__(256, 1) void flash_attn_mma(
    const __nv_bfloat16* __restrict__ qhi, const __nv_bfloat16* __restrict__ qlo,
    const __nv_bfloat16* __restrict__ khi, const __nv_bfloat16* __restrict__ klo,
    const __nv_bfloat16* __restrict__ vhi, const __nv_bfloat16* __restrict__ vlo,
    __nv_bfloat16* __restrict__ ohi, __nv_bfloat16* __restrict__ olo)
{
    extern __shared__ char dsm[];
    const int tid = threadIdx.x;
    const int w = tid >> 5;
    const int lane = tid & 31;
    const int g = lane >> 2;
    const int tq = lane & 3;
    const int qt = (int)(gridDim.x - 1) - (int)blockIdx.x;
    const int b = blockIdx.y >> 4;
    const int h = blockIdx.y & 15;
    const size_t rowbase = (size_t)b * PL * PD + (size_t)h * PDK;

    const uint32_t sQh = smem_u32(dsm + AQ_HI);
    const uint32_t sQl = smem_u32(dsm + AQ_LO);
    const uint32_t sKV = smem_u32(dsm + AKV);

    const int kr0 = tid >> 3;
    const int kc0 = (tid & 7) * 8;

    {
        const uint32_t sb = sKV;
#pragma unroll
        for (int it = 0; it < 2; ++it) {
            const int r = kr0 + it * 32;
            const uint32_t so = (uint32_t)(r * FPITCH + kc0) * 2;
            const size_t go = rowbase + (size_t)r * PD + kc0;
            CP_ASYNC16(sb + AK_HI + so, (const char*)(khi + go));
            CP_ASYNC16(sb + AK_LO + so, (const char*)(klo + go));
            CP_ASYNC16(sb + AV_HI + so, (const char*)(vhi + go));
            CP_ASYNC16(sb + AV_LO + so, (const char*)(vlo + go));
        }
        CP_COMMIT();
    }

#pragma unroll
    for (int it = 0; it < 4; ++it) {
        const int idx = tid + it * 256;
        const int r = idx >> 3;
        const int c = (idx & 7) * 8;
        const size_t go = rowbase + (size_t)(qt * 128 + r) * PD + c;
        const uint32_t so = (uint32_t)(r * FPITCH + c) * 2;
        *(uint4*)(dsm + AQ_HI + so) = *(const uint4*)(qhi + go);
        *(uint4*)(dsm + AQ_LO + so) = *(const uint4*)(qlo + go);
    }
    CP_WAIT0();
    __syncthreads();

    uint32_t qh[4][4], ql[4][4];
    {
        const int row = w * 16 + (lane & 7) + ((lane >> 3) & 1) * 8;
#pragma unroll
        for (int kb = 0; kb < 4; ++kb) {
            const int col = kb * 16 + ((lane >> 4) & 1) * 8;
            const uint32_t off = (uint32_t)(row * FPITCH + col) * 2;
            LDSM_X4(qh[kb][0], qh[kb][1], qh[kb][2], qh[kb][3], sQh + off);
            LDSM_X4(ql[kb][0], ql[kb][1], ql[kb][2], ql[kb][3], sQl + off);
        }
    }

    float oacc[8][4];
#pragma unroll
    for (int nb = 0; nb < 8; ++nb)
#pragma unroll
        for (int e = 0; e < 4; ++e) oacc[nb][e] = 0.0f;
    float m0 = -1.0e30f, m1 = -1.0e30f, l0 = 0.0f, l1 = 0.0f;

    const int jmax = 2 * qt + 1;
    for (int j = 0; j <= jmax; ++j) {
        const int buf = j & 1;
        const uint32_t sb = sKV + buf * KV_STAGE;

        if (j < jmax) {
            const uint32_t nb_ = sKV + (buf ^ 1) * KV_STAGE;
#pragma unroll
            for (int it = 0; it < 2; ++it) {
                const int r = kr0 + it * 32;
                const uint32_t so = (uint32_t)(r * FPITCH + kc0) * 2;
                const size_t go = rowbase + (size_t)((j + 1) * 64 + r) * PD + kc0;
                CP_ASYNC16(nb_ + AK_HI + so, (const char*)(khi + go));
                CP_ASYNC16(nb_ + AK_LO + so, (const char*)(klo + go));
                CP_ASYNC16(nb_ + AV_HI + so, (const char*)(vhi + go));
                CP_ASYNC16(nb_ + AV_LO + so, (const char*)(vlo + go));
            }
            CP_COMMIT();
        }

        float sacc[8][4];
#pragma unroll
        for (int nb = 0; nb < 8; ++nb)
#pragma unroll
            for (int e = 0; e < 4; ++e) sacc[nb][e] = 0.0f;

#pragma unroll
        for (int kb = 0; kb < 4; ++kb) {
            uint32_t kh[8][2], kl[8][2];
            const int kcol = kb * 16 + ((lane >> 3) & 1) * 8;
#pragma unroll
            for (int np = 0; np < 4; ++np) {
                const int krow = np * 16 + (lane & 7) + ((lane >> 4) & 1) * 8;
                const uint32_t off = (uint32_t)(krow * FPITCH + kcol) * 2;
                LDSM_X4(kh[2 * np][0], kh[2 * np][1], kh[2 * np + 1][0], kh[2 * np + 1][1],
                        sb + AK_HI + off);
                LDSM_X4(kl[2 * np][0], kl[2 * np][1], kl[2 * np + 1][0], kl[2 * np + 1][1],
                        sb + AK_LO + off);
            }
#pragma unroll
            for (int nb = 0; nb < 8; ++nb) {
                MMA16816(sacc[nb], qh[kb], kh[nb]);
                MMA16816(sacc[nb], qh[kb], kl[nb]);
                MMA16816(sacc[nb], ql[kb], kh[nb]);
            }
        }

        if (j >= 2 * qt) {
            const int row0 = qt * 128 + w * 16 + g;
            const int row1 = row0 + 8;
            const int cb = j * 64 + 2 * tq;
#pragma unroll
            for (int nb = 0; nb < 8; ++nb) {
                const int c0 = cb + nb * 8, c1 = c0 + 1;
                if (c0 > row0) sacc[nb][0] = -1.0e30f;
                if (c1 > row0) sacc[nb][1] = -1.0e30f;
                if (c0 > row1) sacc[nb][2] = -1.0e30f;
                if (c1 > row1) sacc[nb][3] = -1.0e30f;
            }
        }

        float mx0 = -1.0e30f, mx1 = -1.0e30f;
#pragma unroll
        for (int nb = 0; nb < 8; ++nb) {
            mx0 = fmaxf(mx0, fmaxf(sacc[nb][0], sacc[nb][1]));
            mx1 = fmaxf(mx1, fmaxf(sacc[nb][2], sacc[nb][3]));
        }
        mx0 = fmaxf(mx0, __shfl_xor_sync(0xffffffffu, mx0, 1));
        mx0 = fmaxf(mx0, __shfl_xor_sync(0xffffffffu, mx0, 2));
        mx1 = fmaxf(mx1, __shfl_xor_sync(0xffffffffu, mx1, 1));
        mx1 = fmaxf(mx1, __shfl_xor_sync(0xffffffffu, mx1, 2));

        const float mn0 = fmaxf(m0, mx0);
        const float mn1 = fmaxf(m1, mx1);
        const float em0 = mn0 * SFC;
        const float em1 = mn1 * SFC;
        const float cr0 = ex2f((m0 - mn0) * SFC);
        const float cr1 = ex2f((m1 - mn1) * SFC);
        m0 = mn0; m1 = mn1;

        float s0 = 0.0f, s1 = 0.0f;
#pragma unroll
        for (int nb = 0; nb < 8; ++nb) {
            float p0 = ex2f(fmaf(sacc[nb][0], SFC, -em0));
            float p1 = ex2f(fmaf(sacc[nb][1], SFC, -em0));
            float p2 = ex2f(fmaf(sacc[nb][2], SFC, -em1));
            float p3 = ex2f(fmaf(sacc[nb][3], SFC, -em1));
            sacc[nb][0] = p0; sacc[nb][1] = p1;
            sacc[nb][2] = p2; sacc[nb][3] = p3;
            s0 += p0 + p1; s1 += p2 + p3;
        }
        s0 += __shfl_xor_sync(0xffffffffu, s0, 1);
        s0 += __shfl_xor_sync(0xffffffffu, s0, 2);
        s1 += __shfl_xor_sync(0xffffffffu, s1, 1);
        s1 += __shfl_xor_sync(0xffffffffu, s1, 2);
        l0 = l0 * cr0 + s0;
        l1 = l1 * cr1 + s1;

#pragma unroll
        for (int nb = 0; nb < 8; ++nb) {
            oacc[nb][0] *= cr0; oacc[nb][1] *= cr0;
            oacc[nb][2] *= cr1; oacc[nb][3] *= cr1;
        }

        uint32_t pa[4][4], pl[4][4];
#pragma unroll
        for (int kb = 0; kb < 4; ++kb) {
            split2(sacc[2 * kb][0], sacc[2 * kb][1], pa[kb][0], pl[kb][0]);
            split2(sacc[2 * kb][2], sacc[2 * kb][3], pa[kb][1], pl[kb][1]);
            split2(sacc[2 * kb + 1][0], sacc[2 * kb + 1][1], pa[kb][2], pl[kb][2]);
            split2(sacc[2 * kb + 1][2], sacc[2 * kb + 1][3], pa[kb][3], pl[kb][3]);
        }

#pragma unroll
        for (int kb = 0; kb < 4; ++kb) {
            uint32_t vh[8][2], vl[8][2];
            const int vrow = kb * 16 + (lane & 7) + ((lane >> 3) & 1) * 8;
#pragma unroll
            for (int np = 0; np < 4; ++np) {
                const int vcol = np * 16 + ((lane >> 4) & 1) * 8;
                const uint32_t off = (uint32_t)(vrow * FPITCH + vcol) * 2;
                LDSM_X4_T(vh[2 * np][0], vh[2 * np][1], vh[2 * np + 1][0], vh[2 * np + 1][1],
                          sb + AV_HI + off);
                LDSM_X4_T(vl[2 * np][0], vl[2 * np][1], vl[2 * np + 1][0], vl[2 * np + 1][1],
                          sb + AV_LO + off);
            }
#pragma unroll
            for (int nb = 0; nb < 8; ++nb) {
                MMA16816(oacc[nb], pa[kb], vh[nb]);
                MMA16816(oacc[nb], pa[kb], vl[nb]);
                MMA16816(oacc[nb], pl[kb], vh[nb]);
            }
        }

        if (j < jmax) {
            CP_WAIT0();
            __syncthreads();
        }
    }

    const float inv0 = 1.0f / l0;
    const float inv1 = 1.0f / l1;
    const int row0 = qt * 128 + w * 16 + g;
#pragma unroll
    for (int nb = 0; nb < 8; ++nb) {
        const int col = nb * 8 + 2 * tq;
        uint32_t hi, lo;
        split2(oacc[nb][0] * inv0, oacc[nb][1] * inv0, hi, lo);
        const size_t g0 = rowbase + (size_t)row0 * PD + col;
        *(uint32_t*)(ohi + g0) = hi;
        *(uint32_t*)(olo + g0) = lo;
        split2(oacc[nb][2] * inv1, oacc[nb][3] * inv1, hi, lo);
        const size_t g1 = rowbase + (size_t)(row0 + 8) * PD + col;
        *(uint32_t*)(ohi + g1) = hi;
        *(uint32_t*)(olo + g1) = lo;
    }
}

// ---------------------------------------------------------------------------
extern "C" void kernel_launch(void* const* d_in, const int* in_sizes, int n_in,
                              void* d_out, int out_size)
{
    const float* Q    = (const float*)d_in[0];
    const float* K    = (const float*)d_in[1];
    const float* V    = (const float*)d_in[2];
    const float* Wq_w = (const float*)d_in[4];
    const float* Wq_b = (const float*)d_in[5];
    const float* Wk_w = (const float*)d_in[6];
    const float* Wk_b = (const float*)d_in[7];
    const float* Wv_w = (const float*)d_in[8];
    const float* Wv_b = (const float*)d_in[9];
    const float* fc_w = (const float*)d_in[10];
    const float* fc_b = (const float*)d_in[11];
    float* out = (float*)d_out;

    __nv_bfloat16 *ihi, *ilo, *whi, *wlo, *qhi, *qlo, *khi, *klo, *vhi, *vlo, *ahi, *alo;
    cudaGetSymbolAddress((void**)&ihi, g_ihi);
    cudaGetSymbolAddress((void**)&ilo, g_ilo);
    cudaGetSymbolAddress((void**)&whi, g_whi);
    cudaGetSymbolAddress((void**)&wlo, g_wlo);
    cudaGetSymbolAddress((void**)&qhi, g_qhi);
    cudaGetSymbolAddress((void**)&qlo, g_qlo);
    cudaGetSymbolAddress((void**)&khi, g_khi);
    cudaGetSymbolAddress((void**)&klo, g_klo);
    cudaGetSymbolAddress((void**)&vhi, g_vhi);
    cudaGetSymbolAddress((void**)&vlo, g_vlo);
    cudaGetSymbolAddress((void**)&ahi, g_ahi);
    cudaGetSymbolAddress((void**)&alo, g_alo);

    cudaFuncSetAttribute(gemm3_mma<true>,
                         cudaFuncAttributeMaxDynamicSharedMemorySize, G_SMEM);
    cudaFuncSetAttribute(gemm3_mma<false>,
                         cudaFuncAttributeMaxDynamicSharedMemorySize, G_SMEM);
    cudaFuncSetAttribute(flash_attn_mma,
                         cudaFuncAttributeMaxDynamicSharedMemorySize, ATT_SMEM);

    const int nA4 = PM * PD / 4;
    const int nW4 = PD * PD / 4;
    dim3 ggrid(PD / BGN, PM / BGM);   // (4, 32) = 128 CTAs, single wave

    // Q projection -> qhi/qlo
    split_bf16<<<nA4 / 256, 256>>>(Q, ihi, ilo, nA4);
    split_bf16<<<nW4 / 256, 256>>>(Wq_w, whi, wlo, nW4);
    gemm3_mma<true><<<ggrid, 256, G_SMEM>>>(ihi, ilo, whi, wlo, Wq_b,
                                            nullptr, qhi, qlo, PD, PD);
    // K projection -> khi/klo
    split_bf16<<<nA4 / 256, 256>>>(K, ihi, ilo, nA4);
    split_bf16<<<nW4 / 256, 256>>>(Wk_w, whi, wlo, nW4);
    gemm3_mma<true><<<ggrid, 256, G_SMEM>>>(ihi, ilo, whi, wlo, Wk_b,
                                            nullptr, khi, klo, PD, PD);
    // V projection -> vhi/vlo
    split_bf16<<<nA4 / 256, 256>>>(V, ihi, ilo, nA4);
    split_bf16<<<nW4 / 256, 256>>>(Wv_w, whi, wlo, nW4);
    gemm3_mma<true><<<ggrid, 256, G_SMEM>>>(ihi, ilo, whi, wlo, Wv_b,
                                            nullptr, vhi, vlo, PD, PD);

    // Attention -> ahi/alo
    flash_attn_mma<<<dim3(PL / 128, PB * PH), 256, ATT_SMEM>>>(
        qhi, qlo, khi, klo, vhi, vlo, ahi, alo);

    // Output projection (fp32 out)
    split_bf16<<<nW4 / 256, 256>>>(fc_w, whi, wlo, nW4);
    gemm3_mma<false><<<ggrid, 256, G_SMEM>>>(ahi, alo, whi, wlo, fc_b,
                                             out, nullptr, nullptr, PD, PD);
}

// round 7
// speedup vs baseline: 2.9890x; 1.0766x over previous
#include <cuda_runtime.h>
#include <cuda_bf16.h>
#include <cstdint>
#include <math.h>

// Problem constants
#define PB 2
#define PL 2048
#define PD 1024
#define PH 16
#define PDK 64
#define PM (PB * PL)   // 4096

// Scratch (device globals)
__device__ __nv_bfloat16 g_ihi[PM * PD];   // Q-input split
__device__ __nv_bfloat16 g_ilo[PM * PD];
__device__ __nv_bfloat16 g_jhi[PM * PD];   // K-input split
__device__ __nv_bfloat16 g_jlo[PM * PD];
__device__ __nv_bfloat16 g_ahi[PM * PD];   // V-input split, later attn out
__device__ __nv_bfloat16 g_alo[PM * PD];
__device__ __nv_bfloat16 g_w1hi[PD * PD];  // Wq
__device__ __nv_bfloat16 g_w1lo[PD * PD];
__device__ __nv_bfloat16 g_w2hi[PD * PD];  // Wk
__device__ __nv_bfloat16 g_w2lo[PD * PD];
__device__ __nv_bfloat16 g_w3hi[PD * PD];  // Wv
__device__ __nv_bfloat16 g_w3lo[PD * PD];
__device__ __nv_bfloat16 g_w4hi[PD * PD];  // fc
__device__ __nv_bfloat16 g_w4lo[PD * PD];
__device__ __nv_bfloat16 g_qhi[PM * PD];
__device__ __nv_bfloat16 g_qlo[PM * PD];
__device__ __nv_bfloat16 g_khi[PM * PD];
__device__ __nv_bfloat16 g_klo[PM * PD];
__device__ __nv_bfloat16 g_vhi[PM * PD];
__device__ __nv_bfloat16 g_vlo[PM * PD];

// ---------------------------------------------------------------------------
// PTX helpers (baseline PTX only)
// ---------------------------------------------------------------------------
__device__ __forceinline__ uint32_t smem_u32(const void* p) {
    uint32_t a;
    asm("{ .reg .u64 t; cvta.to.shared.u64 t, %1; cvt.u32.u64 %0, t; }"
        : "=r"(a) : "l"(p));
    return a;
}

#define MMA16816(c, a, b) \
    asm volatile("mma.sync.aligned.m16n8k16.row.col.f32.bf16.bf16.f32 " \
        "{%0,%1,%2,%3}, {%4,%5,%6,%7}, {%8,%9}, {%0,%1,%2,%3};" \
        : "+f"((c)[0]), "+f"((c)[1]), "+f"((c)[2]), "+f"((c)[3]) \
        : "r"((a)[0]), "r"((a)[1]), "r"((a)[2]), "r"((a)[3]), \
          "r"((b)[0]), "r"((b)[1]))

#define LDSM_X4(r0, r1, r2, r3, addr) \
    asm volatile("ldmatrix.sync.aligned.m8n8.x4.shared.b16 {%0,%1,%2,%3}, [%4];" \
        : "=r"(r0), "=r"(r1), "=r"(r2), "=r"(r3) : "r"(addr))

#define LDSM_X4_T(r0, r1, r2, r3, addr) \
    asm volatile("ldmatrix.sync.aligned.m8n8.x4.trans.shared.b16 {%0,%1,%2,%3}, [%4];" \
        : "=r"(r0), "=r"(r1), "=r"(r2), "=r"(r3) : "r"(addr))

#define CP_ASYNC16(smem, gptr) \
    asm volatile("cp.async.cg.shared.global [%0], [%1], 16;" \
        :: "r"(smem), "l"(gptr))
#define CP_COMMIT() asm volatile("cp.async.commit_group;" ::: "memory")
#define CP_WAIT0()  asm volatile("cp.async.wait_group 0;" ::: "memory")

__device__ __forceinline__ float ex2f(float x) {
    float r;
    asm("ex2.approx.f32 %0, %1;" : "=f"(r) : "f"(x));
    return r;
}

__device__ __forceinline__ void split2(float a, float b, uint32_t& hi, uint32_t& lo) {
    __nv_bfloat16 ha = __float2bfloat16(a);
    __nv_bfloat16 hb = __float2bfloat16(b);
    float ra = a - __bfloat162float(ha);
    float rb = b - __bfloat162float(hb);
    __nv_bfloat162 H; H.x = ha; H.y = hb;
    __nv_bfloat162 L; L.x = __float2bfloat16(ra); L.y = __float2bfloat16(rb);
    hi = *reinterpret_cast<uint32_t*>(&H);
    lo = *reinterpret_cast<uint32_t*>(&L);
}

// ---------------------------------------------------------------------------
// Batched splits: grid.z selects which tensor
// ---------------------------------------------------------------------------
__device__ __forceinline__ void split_body(
    const float* x, __nv_bfloat16* hi, __nv_bfloat16* lo, int i)
{
    float4 v = reinterpret_cast<const float4*>(x)[i];
    uint32_t h0, l0, h1, l1;
    split2(v.x, v.y, h0, l0);
    split2(v.z, v.w, h1, l1);
    reinterpret_cast<uint2*>(hi)[i] = make_uint2(h0, h1);
    reinterpret_cast<uint2*>(lo)[i] = make_uint2(l0, l1);
}

__global__ __launch_bounds__(256) void split3_in(
    const float* __restrict__ x0, const float* __restrict__ x1,
    const float* __restrict__ x2,
    __nv_bfloat16* h0, __nv_bfloat16* l0, __nv_bfloat16* h1, __nv_bfloat16* l1,
    __nv_bfloat16* h2, __nv_bfloat16* l2)
{
    const int i = blockIdx.x * 256 + threadIdx.x;
    const int z = blockIdx.z;
    const float* x = (z == 0) ? x0 : (z == 1) ? x1 : x2;
    __nv_bfloat16* hh = (z == 0) ? h0 : (z == 1) ? h1 : h2;
    __nv_bfloat16* ll = (z == 0) ? l0 : (z == 1) ? l1 : l2;
    split_body(x, hh, ll, i);
}

__global__ __launch_bounds__(256) void split4_w(
    const float* __restrict__ x0, const float* __restrict__ x1,
    const float* __restrict__ x2, const float* __restrict__ x3,
    __nv_bfloat16* h0, __nv_bfloat16* l0, __nv_bfloat16* h1, __nv_bfloat16* l1,
    __nv_bfloat16* h2, __nv_bfloat16* l2, __nv_bfloat16* h3, __nv_bfloat16* l3)
{
    const int i = blockIdx.x * 256 + threadIdx.x;
    const int z = blockIdx.z;
    const float* x = (z == 0) ? x0 : (z == 1) ? x1 : (z == 2) ? x2 : x3;
    __nv_bfloat16* hh = (z == 0) ? h0 : (z == 1) ? h1 : (z == 2) ? h2 : h3;
    __nv_bfloat16* ll = (z == 0) ? l0 : (z == 1) ? l1 : (z == 2) ? l2 : l3;
    split_body(x, hh, ll, i);
}

// ---------------------------------------------------------------------------
// mma.sync bf16 GEMM (3-term split): C[m,n] = sum_k A[m,k]*B[n,k] + bias[n]
// 128x256x64 tiles, 8 warps (2m x 4n), 2-stage cp.async pipeline.
// ---------------------------------------------------------------------------
#define BGM 128
#define BGN 256
#define BGK 64
#define GP 72                             // smem pitch (bf16)
#define A_T (BGM * GP * 2)                // 18432 B
#define B_T (BGN * GP * 2)                // 36864 B
#define OFF_GA_HI 0
#define OFF_GA_LO A_T
#define OFF_GB_HI (2 * A_T)
#define OFF_GB_LO (2 * A_T + B_T)
#define STG_B (2 * A_T + 2 * B_T)         // 110592 B
#define G_SMEM (2 * STG_B)                // 221184 B

template <bool SPLIT>
__global__ __launch_bounds__(256, 1) void gemm3_mma(
    const __nv_bfloat16* __restrict__ Ahi, const __nv_bfloat16* __restrict__ Alo,
    const __nv_bfloat16* __restrict__ Bhi, const __nv_bfloat16* __restrict__ Blo,
    const float* __restrict__ bias, float* __restrict__ C,
    __nv_bfloat16* __restrict__ Chi, __nv_bfloat16* __restrict__ Clo,
    int K, int N)
{
    extern __shared__ char dsm[];
    __shared__ float sbias[BGN];

    const int tid = threadIdx.x;
    const int w = tid >> 5;
    const int lane = tid & 31;
    const int wm = w >> 2;
    const int wn = w & 3;
    const int g = lane >> 2;
    const int tq = lane & 3;
    const int bm = blockIdx.y * BGM;
    const int bn = blockIdx.x * BGN;
    const uint32_t sbase = smem_u32(dsm);

    // cp.async load mapping: 64-col chunk, 16B per thread-col
    const int lr = tid >> 3;              // 0..31
    const int lc = (tid & 7) * 8;         // 0..56

    auto issue = [&](int c, int buf) {
        const uint32_t sb = sbase + buf * STG_B;
        const int kofs = c * BGK;
#pragma unroll
        for (int it = 0; it < 4; ++it) {
            const int r = lr + it * 32;
            const uint32_t so = (uint32_t)(r * GP + lc) * 2;
            const size_t go = (size_t)(bm + r) * K + kofs + lc;
            CP_ASYNC16(sb + OFF_GA_HI + so, (const char*)(Ahi + go));
            CP_ASYNC16(sb + OFF_GA_LO + so, (const char*)(Alo + go));
        }
#pragma unroll
        for (int it = 0; it < 8; ++it) {
            const int r = lr + it * 32;
            const uint32_t so = (uint32_t)(r * GP + lc) * 2;
            const size_t go = (size_t)(bn + r) * K + kofs + lc;
            CP_ASYNC16(sb + OFF_GB_HI + so, (const char*)(Bhi + go));
            CP_ASYNC16(sb + OFF_GB_LO + so, (const char*)(Blo + go));
        }
    };

    issue(0, 0); CP_COMMIT();

    sbias[tid] = bias[bn + tid];

    float acc[4][8][4];
#pragma unroll
    for (int mi = 0; mi < 4; ++mi)
#pragma unroll
        for (int nb = 0; nb < 8; ++nb)
#pragma unroll
            for (int e = 0; e < 4; ++e) acc[mi][nb][e] = 0.0f;

    const int a_r = (lane & 7) + ((lane >> 3) & 1) * 8;
    const int a_c = ((lane >> 4) & 1) * 8;
    const int b_r = (lane & 7) + ((lane >> 4) & 1) * 8;
    const int b_c = ((lane >> 3) & 1) * 8;

    const int nchunk = K / BGK;   // 16
    for (int c = 0; c < nchunk; ++c) {
        CP_WAIT0();
        __syncthreads();
        if (c + 1 < nchunk) { issue(c + 1, (c + 1) & 1); CP_COMMIT(); }

        const uint32_t sb = sbase + (c & 1) * STG_B;
#pragma unroll
        for (int kk = 0; kk < 4; ++kk) {
            uint32_t ah[4][4], al[4][4];
#pragma unroll
            for (int mi = 0; mi < 4; ++mi) {
                const uint32_t off =
                    (uint32_t)((wm * 64 + mi * 16 + a_r) * GP + kk * 16 + a_c) * 2;
                LDSM_X4(ah[mi][0], ah[mi][1], ah[mi][2], ah[mi][3],
                        sb + OFF_GA_HI + off);
                LDSM_X4(al[mi][0], al[mi][1], al[mi][2], al[mi][3],
                        sb + OFF_GA_LO + off);
            }
            uint32_t bh[8][2], bl[8][2];
#pragma unroll
            for (int np = 0; np < 4; ++np) {
                const uint32_t off =
                    (uint32_t)((wn * 64 + np * 16 + b_r) * GP + kk * 16 + b_c) * 2;
                LDSM_X4(bh[2 * np][0], bh[2 * np][1], bh[2 * np + 1][0], bh[2 * np + 1][1],
                        sb + OFF_GB_HI + off);
                LDSM_X4(bl[2 * np][0], bl[2 * np][1], bl[2 * np + 1][0], bl[2 * np + 1][1],
                        sb + OFF_GB_LO + off);
            }
#pragma unroll
            for (int mi = 0; mi < 4; ++mi)
#pragma unroll
                for (int nb = 0; nb < 8; ++nb) {
                    MMA16816(acc[mi][nb], ah[mi], bh[nb]);
                    MMA16816(acc[mi][nb], ah[mi], bl[nb]);
                    MMA16816(acc[mi][nb], al[mi], bh[nb]);
                }
        }
    }

    // epilogue: bias add + direct store from registers
#pragma unroll
    for (int mi = 0; mi < 4; ++mi) {
        const int row0 = bm + wm * 64 + mi * 16 + g;
        const int row1 = row0 + 8;
#pragma unroll
        for (int nb = 0; nb < 8; ++nb) {
            const int coll = wn * 64 + nb * 8 + 2 * tq;
            const float b0 = sbias[coll];
            const float b1 = sbias[coll + 1];
            const float v0 = acc[mi][nb][0] + b0;
            const float v1 = acc[mi][nb][1] + b1;
            const float v2 = acc[mi][nb][2] + b0;
            const float v3 = acc[mi][nb][3] + b1;
            const size_t o0 = (size_t)row0 * N + bn + coll;
            const size_t o1 = (size_t)row1 * N + bn + coll;
            if (SPLIT) {
                uint32_t hi, lo;
                split2(v0, v1, hi, lo);
                *(uint32_t*)(Chi + o0) = hi;
                *(uint32_t*)(Clo + o0) = lo;
                split2(v2, v3, hi, lo);
                *(uint32_t*)(Chi + o1) = hi;
                *(uint32_t*)(Clo + o1) = lo;
            } else {
                *(float2*)(C + o0) = make_float2(v0, v1);
                *(float2*)(C + o1) = make_float2(v2, v3);
            }
        }
    }
}

// ---------------------------------------------------------------------------
// Register-resident FA2 on mma.sync — 64-row q-tiles, 128 threads (4 warps),
// occupancy 2. grid = (32, 32), heavy CTAs first.
// ---------------------------------------------------------------------------
#define FPITCH 72
#define AQ_HI 0
#define AQ_LO 9216
#define AKV   18432
#define KV_STAGE 36864
#define AK_HI 0
#define AK_LO 9216
#define AV_HI 18432
#define AV_LO 27648
#define ATT_SMEM (AKV + 2 * KV_STAGE)     // 92160

#define SFC 0.18033688f                   // 0.125 * log2(e)

__global__ __launch_bounds__(128, 2) void flash_attn_mma(
    const __nv_bfloat16* __restrict__ qhi, const __nv_bfloat16* __restrict__ qlo,
    const __nv_bfloat16* __restrict__ khi, const __nv_bfloat16* __restrict__ klo,
    const __nv_bfloat16* __restrict__ vhi, const __nv_bfloat16* __restrict__ vlo,
    __nv_bfloat16* __restrict__ ohi, __nv_bfloat16* __restrict__ olo)
{
    extern __shared__ char dsm[];
    const int tid = threadIdx.x;
    const int w = tid >> 5;               // 0..3
    const int lane = tid & 31;
    const int g = lane >> 2;
    const int tq = lane & 3;
    const int qt = (int)(gridDim.x - 1) - (int)blockIdx.x;   // heavy first
    const int b = blockIdx.y >> 4;
    const int h = blockIdx.y & 15;
    const size_t rowbase = (size_t)b * PL * PD + (size_t)h * PDK;

    const uint32_t sQh = smem_u32(dsm + AQ_HI);
    const uint32_t sQl = smem_u32(dsm + AQ_LO);
    const uint32_t sKV = smem_u32(dsm + AKV);

    // KV cp.async mapping: 64 rows x 64 cols per array, 128 threads
    const int kr0 = tid >> 3;              // 0..15
    const int kc0 = (tid & 7) * 8;

    // prologue: KV tile 0 into buffer 0
    {
        const uint32_t sb = sKV;
#pragma unroll
        for (int it = 0; it < 4; ++it) {
            const int r = kr0 + it * 16;
            const uint32_t so = (uint32_t)(r * FPITCH + kc0) * 2;
            const size_t go = rowbase + (size_t)r * PD + kc0;
            CP_ASYNC16(sb + AK_HI + so, (const char*)(khi + go));
            CP_ASYNC16(sb + AK_LO + so, (const char*)(klo + go));
            CP_ASYNC16(sb + AV_HI + so, (const char*)(vhi + go));
            CP_ASYNC16(sb + AV_LO + so, (const char*)(vlo + go));
        }
        CP_COMMIT();
    }

    // Q tile (64 x 64) hi/lo
#pragma unroll
    for (int it = 0; it < 4; ++it) {
        const int idx = tid + it * 128;
        const int r = idx >> 3;
        const int c = (idx & 7) * 8;
        const size_t go = rowbase + (size_t)(qt * 64 + r) * PD + c;
        const uint32_t so = (uint32_t)(r * FPITCH + c) * 2;
        *(uint4*)(dsm + AQ_HI + so) = *(const uint4*)(qhi + go);
        *(uint4*)(dsm + AQ_LO + so) = *(const uint4*)(qlo + go);
    }
    CP_WAIT0();
    __syncthreads();

    uint32_t qh[4][4], ql[4][4];
    {
        const int row = w * 16 + (lane & 7) + ((lane >> 3) & 1) * 8;
#pragma unroll
        for (int kb = 0; kb < 4; ++kb) {
            const int col = kb * 16 + ((lane >> 4) & 1) * 8;
            const uint32_t off = (uint32_t)(row * FPITCH + col) * 2;
            LDSM_X4(qh[kb][0], qh[kb][1], qh[kb][2], qh[kb][3], sQh + off);
            LDSM_X4(ql[kb][0], ql[kb][1], ql[kb][2], ql[kb][3], sQl + off);
        }
    }

    float oacc[8][4];
#pragma unroll
    for (int nb = 0; nb < 8; ++nb)
#pragma unroll
        for (int e = 0; e < 4; ++e) oacc[nb][e] = 0.0f;
    float m0 = -1.0e30f, m1 = -1.0e30f, l0 = 0.0f, l1 = 0.0f;

    const int jmax = qt;
    for (int j = 0; j <= jmax; ++j) {
        const int buf = j & 1;
        const uint32_t sb = sKV + buf * KV_STAGE;

        if (j < jmax) {
            const uint32_t nb_ = sKV + (buf ^ 1) * KV_STAGE;
#pragma unroll
            for (int it = 0; it < 4; ++it) {
                const int r = kr0 + it * 16;
                const uint32_t so = (uint32_t)(r * FPITCH + kc0) * 2;
                const size_t go = rowbase + (size_t)((j + 1) * 64 + r) * PD + kc0;
                CP_ASYNC16(nb_ + AK_HI + so, (const char*)(khi + go));
                CP_ASYNC16(nb_ + AK_LO + so, (const char*)(klo + go));
                CP_ASYNC16(nb_ + AV_HI + so, (const char*)(vhi + go));
                CP_ASYNC16(nb_ + AV_LO + so, (const char*)(vlo + go));
            }
            CP_COMMIT();
        }

        float sacc[8][4];
#pragma unroll
        for (int nb = 0; nb < 8; ++nb)
#pragma unroll
            for (int e = 0; e < 4; ++e) sacc[nb][e] = 0.0f;

#pragma unroll
        for (int kb = 0; kb < 4; ++kb) {
            uint32_t kh[8][2], kl[8][2];
            const int kcol = kb * 16 + ((lane >> 3) & 1) * 8;
#pragma unroll
            for (int np = 0; np < 4; ++np) {
                const int krow = np * 16 + (lane & 7) + ((lane >> 4) & 1) * 8;
                const uint32_t off = (uint32_t)(krow * FPITCH + kcol) * 2;
                LDSM_X4(kh[2 * np][0], kh[2 * np][1], kh[2 * np + 1][0], kh[2 * np + 1][1],
                        sb + AK_HI + off);
                LDSM_X4(kl[2 * np][0], kl[2 * np][1], kl[2 * np + 1][0], kl[2 * np + 1][1],
                        sb + AK_LO + off);
            }
#pragma unroll
            for (int nb = 0; nb < 8; ++nb) {
                MMA16816(sacc[nb], qh[kb], kh[nb]);
                MMA16816(sacc[nb], qh[kb], kl[nb]);
                MMA16816(sacc[nb], ql[kb], kh[nb]);
            }
        }

        if (j == qt) {   // diagonal tile: mask
            const int row0 = qt * 64 + w * 16 + g;
            const int row1 = row0 + 8;
            const int cb = j * 64 + 2 * tq;
#pragma unroll
            for (int nb = 0; nb < 8; ++nb) {
                const int c0 = cb + nb * 8, c1 = c0 + 1;
                if (c0 > row0) sacc[nb][0] = -1.0e30f;
                if (c1 > row0) sacc[nb][1] = -1.0e30f;
                if (c0 > row1) sacc[nb][2] = -1.0e30f;
                if (c1 > row1) sacc[nb][3] = -1.0e30f;
            }
        }

        float mx0 = -1.0e30f, mx1 = -1.0e30f;
#pragma unroll
        for (int nb = 0; nb < 8; ++nb) {
            mx0 = fmaxf(mx0, fmaxf(sacc[nb][0], sacc[nb][1]));
            mx1 = fmaxf(mx1, fmaxf(sacc[nb][2], sacc[nb][3]));
        }
        mx0 = fmaxf(mx0, __shfl_xor_sync(0xffffffffu, mx0, 1));
        mx0 = fmaxf(mx0, __shfl_xor_sync(0xffffffffu, mx0, 2));
        mx1 = fmaxf(mx1, __shfl_xor_sync(0xffffffffu, mx1, 1));
        mx1 = fmaxf(mx1, __shfl_xor_sync(0xffffffffu, mx1, 2));

        const float mn0 = fmaxf(m0, mx0);
        const float mn1 = fmaxf(m1, mx1);
        const float em0 = mn0 * SFC;
        const float em1 = mn1 * SFC;
        const float cr0 = ex2f((m0 - mn0) * SFC);
        const float cr1 = ex2f((m1 - mn1) * SFC);
        m0 = mn0; m1 = mn1;

        float s0 = 0.0f, s1 = 0.0f;
#pragma unroll
        for (int nb = 0; nb < 8; ++nb) {
            float p0 = ex2f(fmaf(sacc[nb][0], SFC, -em0));
            float p1 = ex2f(fmaf(sacc[nb][1], SFC, -em0));
            float p2 = ex2f(fmaf(sacc[nb][2], SFC, -em1));
            float p3 = ex2f(fmaf(sacc[nb][3], SFC, -em1));
            sacc[nb][0] = p0; sacc[nb][1] = p1;
            sacc[nb][2] = p2; sacc[nb][3] = p3;
            s0 += p0 + p1; s1 += p2 + p3;
        }
        s0 += __shfl_xor_sync(0xffffffffu, s0, 1);
        s0 += __shfl_xor_sync(0xffffffffu, s0, 2);
        s1 += __shfl_xor_sync(0xffffffffu, s1, 1);
        s1 += __shfl_xor_sync(0xffffffffu, s1, 2);
        l0 = l0 * cr0 + s0;
        l1 = l1 * cr1 + s1;

#pragma unroll
        for (int nb = 0; nb < 8; ++nb) {
            oacc[nb][0] *= cr0; oacc[nb][1] *= cr0;
            oacc[nb][2] *= cr1; oacc[nb][3] *= cr1;
        }

        uint32_t pa[4][4], pl[4][4];
#pragma unroll
        for (int kb = 0; kb < 4; ++kb) {
            split2(sacc[2 * kb][0], sacc[2 * kb][1], pa[kb][0], pl[kb][0]);
            split2(sacc[2 * kb][2], sacc[2 * kb][3], pa[kb][1], pl[kb][1]);
            split2(sacc[2 * kb + 1][0], sacc[2 * kb + 1][1], pa[kb][2], pl[kb][2]);
            split2(sacc[2 * kb + 1][2], sacc[2 * kb + 1][3], pa[kb][3], pl[kb][3]);
        }

#pragma unroll
        for (int kb = 0; kb < 4; ++kb) {
            uint32_t vh[8][2], vl[8][2];
            const int vrow = kb * 16 + (lane & 7) + ((lane >> 3) & 1) * 8;
#pragma unroll
            for (int np = 0; np < 4; ++np) {
                const int vcol = np * 16 + ((lane >> 4) & 1) * 8;
                const uint32_t off = (uint32_t)(vrow * FPITCH + vcol) * 2;
                LDSM_X4_T(vh[2 * np][0], vh[2 * np][1], vh[2 * np + 1][0], vh[2 * np + 1][1],
                          sb + AV_HI + off);
                LDSM_X4_T(vl[2 * np][0], vl[2 * np][1], vl[2 * np + 1][0], vl[2 * np + 1][1],
                          sb + AV_LO + off);
            }
#pragma unroll
            for (int nb = 0; nb < 8; ++nb) {
                MMA16816(oacc[nb], pa[kb], vh[nb]);
                MMA16816(oacc[nb], pa[kb], vl[nb]);
                MMA16816(oacc[nb], pl[kb], vh[nb]);
            }
        }

        if (j < jmax) {
            CP_WAIT0();
            __syncthreads();
        }
    }

    // epilogue: normalize, split hi/lo, store
    const float inv0 = 1.0f / l0;
    const float inv1 = 1.0f / l1;
    const int row0 = qt * 64 + w * 16 + g;
#pragma unroll
    for (int nb = 0; nb < 8; ++nb) {
        const int col = nb * 8 + 2 * tq;
        uint32_t hi, lo;
        split2(oacc[nb][0] * inv0, oacc[nb][1] * inv0, hi, lo);
        const size_t g0 = rowbase + (size_t)row0 * PD + col;
        *(uint32_t*)(ohi + g0) = hi;
        *(uint32_t*)(olo + g0) = lo;
        split2(oacc[nb][2] * inv1, oacc[nb][3] * inv1, hi, lo);
        const size_t g1 = rowbase + (size_t)(row0 + 8) * PD + col;
        *(uint32_t*)(ohi + g1) = hi;
        *(uint32_t*)(olo + g1) = lo;
    }
}

// ---------------------------------------------------------------------------
extern "C" void kernel_launch(void* const* d_in, const int* in_sizes, int n_in,
                              void* d_out, int out_size)
{
    const float* Q    = (const float*)d_in[0];
    const float* K    = (const float*)d_in[1];
    const float* V    = (const float*)d_in[2];
    const float* Wq_w = (const float*)d_in[4];
    const float* Wq_b = (const float*)d_in[5];
    const float* Wk_w = (const float*)d_in[6];
    const float* Wk_b = (const float*)d_in[7];
    const float* Wv_w = (const float*)d_in[8];
    const float* Wv_b = (const float*)d_in[9];
    const float* fc_w = (const float*)d_in[10];
    const float* fc_b = (const float*)d_in[11];
    float* out = (float*)d_out;

    __nv_bfloat16 *ihi, *ilo, *jhi, *jlo, *vshi, *vslo;
    __nv_bfloat16 *w1hi, *w1lo, *w2hi, *w2lo, *w3hi, *w3lo, *w4hi, *w4lo;
    __nv_bfloat16 *qhi, *qlo, *khi, *klo, *vhi, *vlo;
    cudaGetSymbolAddress((void**)&ihi, g_ihi);
    cudaGetSymbolAddress((void**)&ilo, g_ilo);
    cudaGetSymbolAddress((void**)&jhi, g_jhi);
    cudaGetSymbolAddress((void**)&jlo, g_jlo);
    cudaGetSymbolAddress((void**)&vshi, g_ahi);
    cudaGetSymbolAddress((void**)&vslo, g_alo);
    cudaGetSymbolAddress((void**)&w1hi, g_w1hi);
    cudaGetSymbolAddress((void**)&w1lo, g_w1lo);
    cudaGetSymbolAddress((void**)&w2hi, g_w2hi);
    cudaGetSymbolAddress((void**)&w2lo, g_w2lo);
    cudaGetSymbolAddress((void**)&w3hi, g_w3hi);
    cudaGetSymbolAddress((void**)&w3lo, g_w3lo);
    cudaGetSymbolAddress((void**)&w4hi, g_w4hi);
    cudaGetSymbolAddress((void**)&w4lo, g_w4lo);
    cudaGetSymbolAddress((void**)&qhi, g_qhi);
    cudaGetSymbolAddress((void**)&qlo, g_qlo);
    cudaGetSymbolAddress((void**)&khi, g_khi);
    cudaGetSymbolAddress((void**)&klo, g_klo);
    cudaGetSymbolAddress((void**)&vhi, g_vhi);
    cudaGetSymbolAddress((void**)&vlo, g_vlo);

    cudaFuncSetAttribute(gemm3_mma<true>,
                         cudaFuncAttributeMaxDynamicSharedMemorySize, G_SMEM);
    cudaFuncSetAttribute(gemm3_mma<false>,
                         cudaFuncAttributeMaxDynamicSharedMemorySize, G_SMEM);
    cudaFuncSetAttribute(flash_attn_mma,
                         cudaFuncAttributeMaxDynamicSharedMemorySize, ATT_SMEM);

    const int nA4 = PM * PD / 4;      // 1M
    const int nW4 = PD * PD / 4;      // 256K
    dim3 ggrid(PD / BGN, PM / BGM);   // (4, 32) = 128 CTAs

    // All splits up front (2 launches)
    split3_in<<<dim3(nA4 / 256, 1, 3), 256>>>(Q, K, V,
                                              ihi, ilo, jhi, jlo, vshi, vslo);
    split4_w<<<dim3(nW4 / 256, 1, 4), 256>>>(Wq_w, Wk_w, Wv_w, fc_w,
                                             w1hi, w1lo, w2hi, w2lo,
                                             w3hi, w3lo, w4hi, w4lo);

    // Projections
    gemm3_mma<true><<<ggrid, 256, G_SMEM>>>(ihi, ilo, w1hi, w1lo, Wq_b,
                                            nullptr, qhi, qlo, PD, PD);
    gemm3_mma<true><<<ggrid, 256, G_SMEM>>>(jhi, jlo, w2hi, w2lo, Wk_b,
                                            nullptr, khi, klo, PD, PD);
    gemm3_mma<true><<<ggrid, 256, G_SMEM>>>(vshi, vslo, w3hi, w3lo, Wv_b,
                                            nullptr, vhi, vlo, PD, PD);

    // Attention -> reuse g_ahi/g_alo (V-input split no longer needed)
    flash_attn_mma<<<dim3(PL / 64, PB * PH), 128, ATT_SMEM>>>(
        qhi, qlo, khi, klo, vhi, vlo, vshi, vslo);

    // Output projection (fp32 out)
    gemm3_mma<false><<<ggrid, 256, G_SMEM>>>(vshi, vslo, w4hi, w4lo, fc_b,
                                             out, nullptr, nullptr, PD, PD);
}